// round 12
// baseline (speedup 1.0000x reference)
#include <cuda_runtime.h>
#include <cuda_fp16.h>
#include <math.h>
#include <stdint.h>

#define Bsz   64
#define Dd    1024
#define DMp   1088
#define Hh    8
#define HDp   136
#define DFFp  2048
#define SEQ   512
#define Rr    487
#define MROWS (Bsz*SEQ)     /* 32768 */
#define GHEADS (Bsz*Hh)     /* 512  */
#define M2    (Bsz*25)      /* 1600 */
#define Ll    2

// ---------------- scratch (device globals) -----------------------------------
__device__ float  g_S  [(size_t)MROWS*DMp];
__device__ __half g_Sh [(size_t)MROWS*DMp];
__device__ __half g_QKVh[(size_t)MROWS*3*DMp];
__device__ __half g_Qh [(size_t)GHEADS*SEQ*HDp];
__device__ __half g_Kh [(size_t)GHEADS*SEQ*HDp];
__device__ __half g_Vth[(size_t)GHEADS*HDp*SEQ];
__device__ __half g_Ph [(size_t)GHEADS*25*SEQ];    // layer-2 compact probs only
__device__ __half g_ATTh[(size_t)MROWS*DMp];
__device__ __half g_FFNh[(size_t)MROWS*DFFp];
__device__ float  g_O  [(size_t)MROWS*DMp];
__device__ float  g_S2 [(size_t)M2*DMp];
__device__ __half g_S2h[(size_t)M2*DMp];
__device__ float  g_O2 [(size_t)M2*DMp];
__device__ float  g_bias[Bsz*SEQ];
__device__ __half g_Wqkvh[(size_t)Ll*3*DMp*DMp];
__device__ __half g_Woh  [(size_t)Ll*DMp*DMp];
__device__ __half g_W1h  [(size_t)Ll*DFFp*DMp];
__device__ __half g_W2h  [(size_t)Ll*DMp*DFFp];

// ---------------- f32 -> f16 convert ------------------------------------------
__global__ void cvt_f2h(const float4* __restrict__ s, __half* __restrict__ d, int n4)
{
    int i = blockIdx.x * blockDim.x + threadIdx.x;
    if (i >= n4) return;
    float4 v = s[i];
    union { __half2 h; uint32_t u; } p0, p1;
    p0.h = __floats2half2_rn(v.x, v.y);
    p1.h = __floats2half2_rn(v.z, v.w);
    *(uint2*)(d + (size_t)i*4) = make_uint2(p0.u, p1.u);
}

// ---------------- build S tensor + mask bias ------------------------------------
__global__ void build_S(const float* __restrict__ q, const float* __restrict__ sa,
                        const float* __restrict__ si, const float* __restrict__ ref,
                        const int* __restrict__ na, const int* __restrict__ ni)
{
    size_t idx = (size_t)blockIdx.x * blockDim.x + threadIdx.x;
    if (idx >= (size_t)MROWS * DMp) return;
    int c = (int)(idx % DMp);
    size_t row = idx / DMp;
    int t = (int)(row % SEQ);
    int b = (int)(row / SEQ);
    float v;
    if (t == 0)       v = (c < Dd) ? q  [(size_t)b*Dd + c]              : 0.f;
    else if (t < 13)  v = (c < Dd) ? sa [((size_t)b*12 + (t-1))*Dd + c] : 1.f;
    else if (t < 25)  v = (c < Dd) ? si [((size_t)b*12 + (t-13))*Dd + c]: -1.f;
    else              v = (c < Dd) ? ref[((size_t)b*Rr + (t-25))*Dd + c]: 0.f;
    g_S[idx]  = v;
    g_Sh[idx] = __float2half_rn(v);
    if (c == 0) {
        int ra = na[b], ri = ni[b];
        bool m = (t == 0)
              || (t >= 1  && t < 13 && t < ra + 1)
              || (t >= 13 && t < 25 && t < ri + 13);
        g_bias[b*SEQ + t] = m ? -1.0e9f : 0.f;
    }
}

// ================= fp16 tensor-core GEMM engine v9 ===========================
#define SMKH 24
#define NSTG 4
#define TCSMEM (2 * NSTG * 128 * SMKH * 2)   /* 49152 B */

typedef __half TcTile[128][SMKH];

__device__ __forceinline__ uint32_t smem_u32(const void* p) {
    return (uint32_t)__cvta_generic_to_shared(p);
}

__device__ __forceinline__ void cpa16(uint32_t dst, const __half* src, bool pred) {
    int sz = pred ? 16 : 0;
    asm volatile("cp.async.cg.shared.global [%0], [%1], 16, %2;\n"
                 :: "r"(dst), "l"(src), "r"(sz));
}
#define CP_COMMIT() asm volatile("cp.async.commit_group;\n" ::)
#define CP_WAIT(N)  asm volatile("cp.async.wait_group %0;\n" :: "n"(N))

#define LDSM_X4(r0,r1,r2,r3,addr) \
    asm volatile("ldmatrix.sync.aligned.m8n8.x4.shared.b16 {%0,%1,%2,%3}, [%4];" \
                 : "=r"(r0),"=r"(r1),"=r"(r2),"=r"(r3) : "r"(addr))

__device__ __forceinline__ void mma_f16(float (&d)[4], const uint32_t (&a)[4],
                                        const uint32_t (&b)[2]) {
    asm volatile(
        "mma.sync.aligned.m16n8k16.row.col.f32.f16.f16.f32 "
        "{%0,%1,%2,%3}, {%4,%5,%6,%7}, {%8,%9}, {%0,%1,%2,%3};"
        : "+f"(d[0]), "+f"(d[1]), "+f"(d[2]), "+f"(d[3])
        : "r"(a[0]), "r"(a[1]), "r"(a[2]), "r"(a[3]), "r"(b[0]), "r"(b[1]));
}

__device__ __forceinline__ void tc4_step(
    float (&acc)[4][4][4], const TcTile& As, const TcTile& Bs,
    int mb, int nb, int lane)
{
    uint32_t b[4][2];
    {
        int row = nb + ((lane >> 4) << 3) + (lane & 7);
        int kh  = ((lane >> 3) & 1) * 8;
        LDSM_X4(b[0][0], b[0][1], b[1][0], b[1][1], smem_u32(&Bs[row][kh]));
        LDSM_X4(b[2][0], b[2][1], b[3][0], b[3][1], smem_u32(&Bs[row + 16][kh]));
    }
    int arow = (lane & 15);
    int akh  = (lane >> 4) * 8;
    #pragma unroll
    for (int mi = 0; mi < 4; mi++) {
        uint32_t a[4];
        LDSM_X4(a[0], a[1], a[2], a[3], smem_u32(&As[mb + mi*16 + arow][akh]));
        #pragma unroll
        for (int ni = 0; ni < 4; ni++)
            mma_f16(acc[mi][ni], a, b[ni]);
    }
}

__device__ __forceinline__ void tc4_loop_f16(
    const __half* __restrict__ A, const __half* __restrict__ Bw,
    int K, int M, int N, int bm, int bn,
    float (&acc)[4][4][4], TcTile* As, TcTile* Bs, int tid)
{
    int lane = tid & 31, wid = tid >> 5;
    int mb = (wid >> 2) * 64, nb = (wid & 3) * 32;
    int rr = tid >> 1;
    int lch = (tid & 1) * 8;

    int ar = bm + rr, br = bn + rr;
    bool av = ar < M, bv = br < N;
    const __half* Aprow = A  + (size_t)(av ? ar : 0) * K + lch;
    const __half* Bprow = Bw + (size_t)(bv ? br : 0) * K + lch;

    int chunks = (K + 15) / 16;

    #pragma unroll
    for (int s = 0; s < 3; s++) {
        int k0 = s * 16;
        bool kok = (k0 + lch) < K;
        cpa16(smem_u32(&As[s][rr][lch]), Aprow + k0, kok && av);
        cpa16(smem_u32(&Bs[s][rr][lch]), Bprow + k0, kok && bv);
        CP_COMMIT();
    }

    int buf = 0;
    for (int c = 0; c < chunks; c++) {
        if (c + 1 >= chunks)      { CP_WAIT(0); }
        else if (c + 2 >= chunks) { CP_WAIT(1); }
        else                      { CP_WAIT(2); }
        __syncthreads();
        int kn = (c + 3) * 16;
        if (kn < K) {
            bool kok = (kn + lch) < K;
            int nbuf = (buf + 3) & 3;
            cpa16(smem_u32(&As[nbuf][rr][lch]), Aprow + kn, kok && av);
            cpa16(smem_u32(&Bs[nbuf][rr][lch]), Bprow + kn, kok && bv);
            CP_COMMIT();
        }
        tc4_step(acc, As[buf], Bs[buf], mb, nb, lane);
        buf = (buf + 1) & 3;
    }
}

// ---------------- generic fp16 GEMM: C = A @ W^T + bias, relu, f32/f16 out ----
__global__ void __launch_bounds__(256, 2)
gemm_nt_h(const __half* __restrict__ A, const __half* __restrict__ Bw,
          const float* __restrict__ bias, void* __restrict__ Cv,
          int M, int N, int K, int relu, int outHalf)
{
    extern __shared__ __align__(16) char dsm[];
    TcTile* As = reinterpret_cast<TcTile*>(dsm);
    TcTile* Bs = reinterpret_cast<TcTile*>(dsm + NSTG * 128 * SMKH * 2);
    int tid = threadIdx.x, lane = tid & 31, wid = tid >> 5;
    int mb = (wid >> 2) * 64, nb = (wid & 3) * 32;
    int gid = lane >> 2, tig = lane & 3;
    int bm = blockIdx.y * 128, bn = blockIdx.x * 128;
    float acc[4][4][4] = {};
    tc4_loop_f16(A, Bw, K, M, N, bm, bn, acc, As, Bs, tid);
    #pragma unroll
    for (int mi = 0; mi < 4; mi++) {
        int row = bm + mb + mi*16 + gid;
        #pragma unroll
        for (int ni = 0; ni < 4; ni++) {
            int col = bn + nb + ni*8 + tig*2;
            if (col >= N) continue;
            float b0 = bias[col], b1 = bias[col+1];
            float v0 = acc[mi][ni][0] + b0, v1 = acc[mi][ni][1] + b1;
            float v2 = acc[mi][ni][2] + b0, v3 = acc[mi][ni][3] + b1;
            if (relu) {
                v0 = fmaxf(v0, 0.f); v1 = fmaxf(v1, 0.f);
                v2 = fmaxf(v2, 0.f); v3 = fmaxf(v3, 0.f);
            }
            if (outHalf) {
                __half* C = (__half*)Cv;
                if (row < M)     *(__half2*)(C + (size_t)row * N + col)       = __floats2half2_rn(v0, v1);
                if (row + 8 < M) *(__half2*)(C + (size_t)(row + 8) * N + col) = __floats2half2_rn(v2, v3);
            } else {
                float* C = (float*)Cv;
                if (row < M)     *(float2*)(C + (size_t)row * N + col)       = make_float2(v0, v1);
                if (row + 8 < M) *(float2*)(C + (size_t)(row + 8) * N + col) = make_float2(v2, v3);
            }
        }
    }
}

// ================= fused layer-1 attention ====================================
// One block: head g x 64 query rows. Q resident smem; scores -> smem P;
// warp softmax in smem; O = P @ V^T streamed. No gmem P.
#define QSTR 152          /* Q smem stride (halves): 12r mod 32 bank starts */
#define PSTR 536          /* P smem stride (halves): 12r mod 32 bank starts */
#define QS_BYTES (64*QSTR*2)              /* 19456 */
#define PS_BYTES (64*PSTR*2)              /* 68608 */
#define FBS_BYTES (3*128*SMKH*2)          /* 18432 */
#define FASMEM (QS_BYTES + PS_BYTES + FBS_BYTES)   /* 106496 */

// warp-tile step: acc[2][4][4], A from arbitrary-stride smem, B from staged tile
__device__ __forceinline__ void tcf_step(
    float (&acc)[2][4][4], const __half* Aq, int astr,
    const TcTile& Bs, int mb, int nb, int lane, int akbase)
{
    uint32_t b[4][2];
    {
        int row = nb + ((lane >> 4) << 3) + (lane & 7);
        int kh  = ((lane >> 3) & 1) * 8;
        LDSM_X4(b[0][0], b[0][1], b[1][0], b[1][1], smem_u32(&Bs[row][kh]));
        LDSM_X4(b[2][0], b[2][1], b[3][0], b[3][1], smem_u32(&Bs[row + 16][kh]));
    }
    int arow = lane & 15;
    int akh  = akbase + (lane >> 4) * 8;
    #pragma unroll
    for (int mi = 0; mi < 2; mi++) {
        uint32_t a[4];
        LDSM_X4(a[0], a[1], a[2], a[3],
                smem_u32(Aq + (size_t)(mb + mi*16 + arow) * astr + akh));
        #pragma unroll
        for (int ni = 0; ni < 4; ni++)
            mma_f16(acc[mi][ni], a, b[ni]);
    }
}

// B-only staged k-loop over resident A
__device__ __forceinline__ void tcf_loop(
    const __half* Aq, int astr,
    const __half* __restrict__ Bsrc, int ldb, int brow0, int Nb, int K,
    float (&acc)[2][4][4], TcTile* Bs, int mb, int nb, int tid)
{
    __syncthreads();   // protect Bs reuse across phases
    int lane = tid & 31;
    int rr = tid >> 1, lch = (tid & 1) * 8;
    int br = brow0 + rr;
    bool bv = br < Nb;
    const __half* Brow = Bsrc + (size_t)(bv ? br : 0) * ldb + lch;
    int chunks = (K + 15) / 16;

    #pragma unroll
    for (int s = 0; s < 2; s++) {
        int k0 = s * 16;
        cpa16(smem_u32(&Bs[s][rr][lch]), Brow + k0, bv && (k0 + lch) < K);
        CP_COMMIT();
    }
    int buf = 0;
    for (int c = 0; c < chunks; c++) {
        if (c + 1 >= chunks) { CP_WAIT(0); } else { CP_WAIT(1); }
        __syncthreads();
        int kn = (c + 2) * 16;
        if (kn < K) {
            int nbuf = buf + 2; if (nbuf >= 3) nbuf -= 3;
            cpa16(smem_u32(&Bs[nbuf][rr][lch]), Brow + kn, bv && (kn + lch) < K);
            CP_COMMIT();
        }
        tcf_step(acc, Aq, astr, Bs[buf], mb, nb, lane, c*16);
        if (++buf == 3) buf = 0;
    }
}

__global__ void __launch_bounds__(256, 2) fused_attn()
{
    extern __shared__ __align__(16) char dsm[];
    __half* Qs = (__half*)dsm;                         // [64][QSTR]
    __half* Ps = (__half*)(dsm + QS_BYTES);            // [64][PSTR]
    TcTile* Bs = (TcTile*)(dsm + QS_BYTES + PS_BYTES); // [3][128][SMKH]
    int qb = blockIdx.x, g = blockIdx.y;
    int b = g >> 3, h = g & 7;
    int tid = threadIdx.x, lane = tid & 31, wid = tid >> 5;
    int mb = (wid >> 2) * 32, nb = (wid & 3) * 32;
    int gid = lane >> 2, tig = lane & 3;

    // load Q tile (64 x 136), zero-pad cols 136..151
    const __half* Qsrc = g_Qh + ((size_t)g * SEQ + qb * 64) * HDp;
    for (int idx = tid; idx < 64 * 19; idx += 256) {
        int row = idx / 19, grp = idx % 19;
        uint4 v = make_uint4(0u,0u,0u,0u);
        if (grp < 17) v = *(const uint4*)(Qsrc + (size_t)row * HDp + grp * 8);
        *(uint4*)(Qs + (size_t)row * QSTR + grp * 8) = v;
    }

    const float scale = rsqrtf((float)HDp);
    // scores: 4 key-blocks of 128
    for (int kb = 0; kb < 4; kb++) {
        float acc[2][4][4] = {};
        tcf_loop(Qs, QSTR, g_Kh + (size_t)g * SEQ * HDp, HDp, kb*128, SEQ, HDp,
                 acc, Bs, mb, nb, tid);
        #pragma unroll
        for (int mi = 0; mi < 2; mi++) {
            int row = mb + mi*16 + gid;
            #pragma unroll
            for (int ni = 0; ni < 4; ni++) {
                int col = kb*128 + nb + ni*8 + tig*2;
                float b0 = g_bias[b*SEQ + col], b1 = g_bias[b*SEQ + col + 1];
                *(__half2*)(Ps + (size_t)row*PSTR + col) =
                    __floats2half2_rn(acc[mi][ni][0]*scale + b0, acc[mi][ni][1]*scale + b1);
                *(__half2*)(Ps + (size_t)(row+8)*PSTR + col) =
                    __floats2half2_rn(acc[mi][ni][2]*scale + b0, acc[mi][ni][3]*scale + b1);
            }
        }
    }
    __syncthreads();

    // softmax in smem: warp per row, 8 rows per warp
    for (int r = wid*8; r < wid*8 + 8; r++) {
        __half* p = Ps + (size_t)r * PSTR + lane * 16;
        uint4 u0 = *(const uint4*)(p);
        uint4 u1 = *(const uint4*)(p + 8);
        float v[16];
        {
            const uint32_t* w0 = (const uint32_t*)&u0;
            const uint32_t* w1 = (const uint32_t*)&u1;
            #pragma unroll
            for (int i = 0; i < 4; i++) {
                float2 a = __half22float2(*(const __half2*)&w0[i]);
                float2 bb = __half22float2(*(const __half2*)&w1[i]);
                v[2*i]   = a.x;  v[2*i+1]   = a.y;
                v[8+2*i] = bb.x; v[8+2*i+1] = bb.y;
            }
        }
        float m = v[0];
        #pragma unroll
        for (int i = 1; i < 16; i++) m = fmaxf(m, v[i]);
        #pragma unroll
        for (int off = 16; off > 0; off >>= 1)
            m = fmaxf(m, __shfl_xor_sync(0xffffffffu, m, off));
        float s = 0.f;
        #pragma unroll
        for (int i = 0; i < 16; i++) { v[i] = expf(v[i] - m); s += v[i]; }
        #pragma unroll
        for (int off = 16; off > 0; off >>= 1)
            s += __shfl_xor_sync(0xffffffffu, s, off);
        float inv = 1.f / s;
        uint4 o0, o1;
        {
            uint32_t* w0 = (uint32_t*)&o0;
            uint32_t* w1 = (uint32_t*)&o1;
            #pragma unroll
            for (int i = 0; i < 4; i++) {
                __half2 a = __floats2half2_rn(v[2*i]*inv,   v[2*i+1]*inv);
                __half2 bb = __floats2half2_rn(v[8+2*i]*inv, v[8+2*i+1]*inv);
                w0[i] = *(uint32_t*)&a;
                w1[i] = *(uint32_t*)&bb;
            }
        }
        *(uint4*)(p)     = o0;
        *(uint4*)(p + 8) = o1;
    }

    // O = P @ V^T: 2 n-passes over Vt rows (0..127, 128..135)
    for (int pass = 0; pass < 2; pass++) {
        float acc[2][4][4] = {};
        tcf_loop(Ps, PSTR, g_Vth + (size_t)g * HDp * SEQ, SEQ, pass*128, HDp, SEQ,
                 acc, Bs, mb, nb, tid);
        #pragma unroll
        for (int mi = 0; mi < 2; mi++) {
            int t = qb*64 + mb + mi*16 + gid;
            #pragma unroll
            for (int ni = 0; ni < 4; ni++) {
                int col = pass*128 + nb + ni*8 + tig*2;
                if (col >= HDp) continue;
                __half* base = g_ATTh + ((size_t)b*SEQ + t) * DMp + h*HDp + col;
                *(__half2*)(base) = __floats2half2_rn(acc[mi][ni][0], acc[mi][ni][1]);
                *(__half2*)(base + (size_t)8*DMp) = __floats2half2_rn(acc[mi][ni][2], acc[mi][ni][3]);
            }
        }
    }
}

// ---------------- unpack kernels ------------------------------------------------
__global__ void unpack_qk()
{
    size_t idx = (size_t)blockIdx.x * blockDim.x + threadIdx.x;
    if (idx >= (size_t)MROWS * DMp) return;
    int c = (int)(idx % DMp);
    size_t row = idx / DMp;
    int t = (int)(row % SEQ);
    int b = (int)(row / SEQ);
    int h = c / HDp, d = c % HDp;
    const __half* src = g_QKVh + row * (size_t)(3*DMp);
    size_t gh = (size_t)(b*Hh + h);
    g_Qh[(gh*SEQ + t)*HDp + d] = src[c];
    g_Kh[(gh*SEQ + t)*HDp + d] = src[DMp + c];
}

__global__ void unpack_k()
{
    size_t idx = (size_t)blockIdx.x * blockDim.x + threadIdx.x;
    if (idx >= (size_t)MROWS * DMp) return;
    int c = (int)(idx % DMp);
    size_t row = idx / DMp;
    int t = (int)(row % SEQ);
    int b = (int)(row / SEQ);
    int h = c / HDp, d = c % HDp;
    g_Kh[((size_t)(b*Hh + h)*SEQ + t)*HDp + d] = g_QKVh[row * (size_t)(2*DMp) + c];
}

__global__ void transpose_v(int rowW, int colOff)
{
    __shared__ __half tile[32][33];
    int gh = blockIdx.z;
    int b = gh >> 3, h = gh & 7;
    int t0 = blockIdx.x * 32, d0 = blockIdx.y * 32;
    int tx = threadIdx.x, ty = threadIdx.y;
    const __half* src = g_QKVh + (size_t)b * SEQ * rowW + colOff + h * HDp;
    #pragma unroll
    for (int i = 0; i < 4; i++) {
        int t = t0 + ty + i*8;
        int d = d0 + tx;
        if (d < HDp) tile[ty + i*8][tx] = src[(size_t)t * rowW + d];
    }
    __syncthreads();
    #pragma unroll
    for (int i = 0; i < 4; i++) {
        int d = d0 + ty + i*8;
        int t = t0 + tx;
        if (d < HDp) g_Vth[((size_t)gh*HDp + d)*SEQ + t] = tile[tx][ty + i*8];
    }
}

__global__ void gather_S2()
{
    size_t idx = (size_t)blockIdx.x * blockDim.x + threadIdx.x;
    if (idx >= (size_t)M2 * DMp) return;
    int c = (int)(idx % DMp);
    int i = (int)(idx / DMp);
    int t = i % 25, b = i / 25;
    float v = g_S[((size_t)b*SEQ + t)*DMp + c];
    g_S2[idx]  = v;
    g_S2h[idx] = __float2half_rn(v);
}

__global__ void unpack_q25()
{
    size_t idx = (size_t)blockIdx.x * blockDim.x + threadIdx.x;
    if (idx >= (size_t)M2 * DMp) return;
    int c = (int)(idx % DMp);
    int i = (int)(idx / DMp);
    int t = i % 25, b = i / 25;
    int h = c / HDp, d = c % HDp;
    int g = b*Hh + h;
    g_Qh[((size_t)g*25 + t)*HDp + d] = g_FFNh[(size_t)i*DMp + c];
}

__device__ __forceinline__ float4 ldh4(const __half* p) {
    uint2 u = *(const uint2*)p;
    float2 f0 = __half22float2(*(__half2*)&u.x), f1 = __half22float2(*(__half2*)&u.y);
    return make_float4(f0.x, f0.y, f1.x, f1.y);
}

// ---------------- layer-2 compact scores --------------------------------------
__global__ void __launch_bounds__(256) gemm_scores25()
{
    __shared__ float Qs[8][32];
    __shared__ float Ks[8][128];
    int g = blockIdx.y, b = g >> 3;
    int bn = blockIdx.x * 128;
    int tid = threadIdx.x;
    int lr = tid >> 1, lc = (tid & 1) * 4;
    int col = tid & 127, rg = tid >> 7;
    float acc[13];
    #pragma unroll
    for (int i = 0; i < 13; i++) acc[i] = 0.f;
    for (int k0 = 0; k0 < HDp; k0 += 8) {
        float4 kv = ldh4(g_Kh + ((size_t)g*SEQ + bn + lr)*HDp + k0 + lc);
        Ks[lc+0][lr]=kv.x; Ks[lc+1][lr]=kv.y; Ks[lc+2][lr]=kv.z; Ks[lc+3][lr]=kv.w;
        if (tid < 50) {
            int qr = tid >> 1;
            float4 qv = ldh4(g_Qh + ((size_t)g*25 + qr)*HDp + k0 + lc);
            Qs[lc+0][qr]=qv.x; Qs[lc+1][qr]=qv.y; Qs[lc+2][qr]=qv.z; Qs[lc+3][qr]=qv.w;
        }
        __syncthreads();
        #pragma unroll
        for (int kk = 0; kk < 8; kk++) {
            float bvv = Ks[kk][col];
            #pragma unroll
            for (int i = 0; i < 13; i++) {
                int r = rg + 2*i;
                if (r < 25) acc[i] = fmaf(Qs[kk][r], bvv, acc[i]);
            }
        }
        __syncthreads();
    }
    const float scale = rsqrtf((float)HDp);
    float bias = g_bias[b*SEQ + bn + col];
    #pragma unroll
    for (int i = 0; i < 13; i++) {
        int r = rg + 2*i;
        if (r < 25)
            g_Ph[((size_t)g*25 + r)*SEQ + bn + col] = __float2half_rn(acc[i]*scale + bias);
    }
}

// ---------------- warp-per-row softmax over g_Ph (layer 2 only) ---------------
__global__ void softmax_rows(int nrows)
{
    int row = blockIdx.x * 8 + (threadIdx.x >> 5);
    if (row >= nrows) return;
    int lane = threadIdx.x & 31;
    __half* p = g_Ph + (size_t)row * SEQ + lane * 16;
    uint4 u0 = *(const uint4*)(p);
    uint4 u1 = *(const uint4*)(p + 8);
    float v[16];
    {
        const uint32_t* w0 = (const uint32_t*)&u0;
        const uint32_t* w1 = (const uint32_t*)&u1;
        #pragma unroll
        for (int i = 0; i < 4; i++) {
            float2 a = __half22float2(*(const __half2*)&w0[i]);
            float2 b = __half22float2(*(const __half2*)&w1[i]);
            v[2*i]   = a.x; v[2*i+1]   = a.y;
            v[8+2*i] = b.x; v[8+2*i+1] = b.y;
        }
    }
    float m = v[0];
    #pragma unroll
    for (int i = 1; i < 16; i++) m = fmaxf(m, v[i]);
    #pragma unroll
    for (int off = 16; off > 0; off >>= 1)
        m = fmaxf(m, __shfl_xor_sync(0xffffffffu, m, off));
    float s = 0.f;
    #pragma unroll
    for (int i = 0; i < 16; i++) { v[i] = expf(v[i] - m); s += v[i]; }
    #pragma unroll
    for (int off = 16; off > 0; off >>= 1)
        s += __shfl_xor_sync(0xffffffffu, s, off);
    float inv = 1.f / s;
    uint4 o0, o1;
    {
        uint32_t* w0 = (uint32_t*)&o0;
        uint32_t* w1 = (uint32_t*)&o1;
        #pragma unroll
        for (int i = 0; i < 4; i++) {
            __half2 a = __floats2half2_rn(v[2*i]*inv,   v[2*i+1]*inv);
            __half2 b = __floats2half2_rn(v[8+2*i]*inv, v[8+2*i+1]*inv);
            w0[i] = *(uint32_t*)&a;
            w1[i] = *(uint32_t*)&b;
        }
    }
    *(uint4*)(p)     = o0;
    *(uint4*)(p + 8) = o1;
}

// ---------------- layer-2 compact O = P @ V -------------------------------------
__global__ void __launch_bounds__(160) gemm_av25()
{
    int blk = blockIdx.x;
    int g = blk / 25, r = blk % 25;
    int b = g >> 3, h = g & 7;
    __shared__ float Ps[512];
    const __half* prow = g_Ph + ((size_t)g*25 + r)*SEQ;
    int tid = threadIdx.x;
    for (int i = tid; i < SEQ; i += 160) Ps[i] = __half2float(prow[i]);
    __syncthreads();
    if (tid < HDp) {
        const __half* v = g_Vth + ((size_t)g*HDp + tid)*SEQ;
        float s = 0.f;
        #pragma unroll 4
        for (int t = 0; t < SEQ; t += 8) {
            uint4 u = *(const uint4*)(v + t);
            float2 f0 = __half22float2(*(__half2*)&u.x);
            float2 f1 = __half22float2(*(__half2*)&u.y);
            float2 f2 = __half22float2(*(__half2*)&u.z);
            float2 f3 = __half22float2(*(__half2*)&u.w);
            s = fmaf(Ps[t],   f0.x, s); s = fmaf(Ps[t+1], f0.y, s);
            s = fmaf(Ps[t+2], f1.x, s); s = fmaf(Ps[t+3], f1.y, s);
            s = fmaf(Ps[t+4], f2.x, s); s = fmaf(Ps[t+5], f2.y, s);
            s = fmaf(Ps[t+6], f3.x, s); s = fmaf(Ps[t+7], f3.y, s);
        }
        g_ATTh[((size_t)b*25 + r)*DMp + h*HDp + tid] = __float2half_rn(s);
    }
}

// ---------------- residual add + layernorm ---------------------------------------
__global__ void add_ln(float* __restrict__ x, __half* __restrict__ xh,
                       const float* __restrict__ o,
                       const float* __restrict__ w, const float* __restrict__ bb)
{
    size_t row = blockIdx.x;
    float* xr = x + row * DMp;
    __half* xhr = xh + row * DMp;
    const float* orow = o + row * DMp;
    int tid = threadIdx.x;
    float vals[5];
    int cnt = 0;
    float s = 0.f;
    for (int i = tid; i < DMp; i += 256) { float v = xr[i] + orow[i]; vals[cnt++] = v; s += v; }
    __shared__ float red[256];
    red[tid] = s; __syncthreads();
    for (int st = 128; st > 0; st >>= 1) { if (tid < st) red[tid] += red[tid + st]; __syncthreads(); }
    float mu = red[0] * (1.f / DMp);
    __syncthreads();
    float s2 = 0.f;
    for (int k = 0; k < cnt; k++) { float d = vals[k] - mu; s2 += d * d; }
    red[tid] = s2; __syncthreads();
    for (int st = 128; st > 0; st >>= 1) { if (tid < st) red[tid] += red[tid + st]; __syncthreads(); }
    float rstd = rsqrtf(red[0] * (1.f / DMp) + 1e-5f);
    int k = 0;
    for (int i = tid; i < DMp; i += 256, k++) {
        float r = (vals[k] - mu) * rstd * w[i] + bb[i];
        xr[i] = r;
        xhr[i] = __float2half_rn(r);
    }
}

// ---------------- gather outputs --------------------------------------------------
__global__ void gather_out(float* __restrict__ out)
{
    size_t idx = (size_t)blockIdx.x * blockDim.x + threadIdx.x;
    if (idx >= (size_t)Bsz * 25 * 1024) return;
    int c = (int)(idx % 1024);
    int rem = (int)(idx / 1024);
    int t = rem % 25;
    int b = rem / 25;
    float v = g_S2[((size_t)b*25 + t) * DMp + c];
    size_t o;
    if (t == 0)      o = (size_t)b * 1024 + c;
    else if (t < 13) o = (size_t)Bsz*1024 + ((size_t)b*12 + (t-1))*1024 + c;
    else             o = (size_t)Bsz*1024 + (size_t)Bsz*12*1024
                       + ((size_t)b*12 + (t-13))*1024 + c;
    out[o] = v;
}

// ---------------- launch ----------------------------------------------------------
extern "C" void kernel_launch(void* const* d_in, const int* in_sizes, int n_in,
                              void* d_out, int out_size)
{
    (void)in_sizes; (void)n_in; (void)out_size;
    const float* q    = (const float*)d_in[0];
    const float* sa   = (const float*)d_in[1];
    const float* si   = (const float*)d_in[2];
    const int*   na   = (const int*)  d_in[3];
    const int*   ni   = (const int*)  d_in[4];
    const float* ref  = (const float*)d_in[5];
    const float* Wqkv = (const float*)d_in[6];
    const float* bqkv = (const float*)d_in[7];
    const float* Wo   = (const float*)d_in[8];
    const float* bo   = (const float*)d_in[9];
    const float* ln1w = (const float*)d_in[10];
    const float* ln1b = (const float*)d_in[11];
    const float* W1   = (const float*)d_in[12];
    const float* b1   = (const float*)d_in[13];
    const float* W2   = (const float*)d_in[14];
    const float* b2   = (const float*)d_in[15];
    const float* ln2w = (const float*)d_in[16];
    const float* ln2b = (const float*)d_in[17];

    float *S, *O, *S2, *O2;
    __half *Sh, *QKVh, *ATTh, *FFNh, *S2h, *Wqkvh, *Woh, *W1h, *W2h;
    cudaGetSymbolAddress((void**)&S,    g_S);
    cudaGetSymbolAddress((void**)&Sh,   g_Sh);
    cudaGetSymbolAddress((void**)&QKVh, g_QKVh);
    cudaGetSymbolAddress((void**)&ATTh, g_ATTh);
    cudaGetSymbolAddress((void**)&FFNh, g_FFNh);
    cudaGetSymbolAddress((void**)&O,    g_O);
    cudaGetSymbolAddress((void**)&S2,   g_S2);
    cudaGetSymbolAddress((void**)&S2h,  g_S2h);
    cudaGetSymbolAddress((void**)&O2,   g_O2);
    cudaGetSymbolAddress((void**)&Wqkvh, g_Wqkvh);
    cudaGetSymbolAddress((void**)&Woh,   g_Woh);
    cudaGetSymbolAddress((void**)&W1h,   g_W1h);
    cudaGetSymbolAddress((void**)&W2h,   g_W2h);

    cudaFuncSetAttribute(gemm_nt_h,  cudaFuncAttributeMaxDynamicSharedMemorySize, TCSMEM);
    cudaFuncSetAttribute(fused_attn, cudaFuncAttributeMaxDynamicSharedMemorySize, FASMEM);

    // weight conversion (f32 -> f16)
    {
        int n;
        n = Ll*3*DMp*DMp/4; cvt_f2h<<<(n+255)/256, 256>>>((const float4*)Wqkv, Wqkvh, n);
        n = Ll*DMp*DMp/4;   cvt_f2h<<<(n+255)/256, 256>>>((const float4*)Wo,   Woh,   n);
        n = Ll*DFFp*DMp/4;  cvt_f2h<<<(n+255)/256, 256>>>((const float4*)W1,   W1h,   n);
        n = Ll*DMp*DFFp/4;  cvt_f2h<<<(n+255)/256, 256>>>((const float4*)W2,   W2h,   n);
    }

    const int elems = MROWS * DMp;
    build_S<<<elems/256, 256>>>(q, sa, si, ref, na, ni);

    // ===================== Layer 0: full 512-token path =====================
    {
        gemm_nt_h<<<dim3((3*DMp + 127)/128, MROWS/128), 256, TCSMEM>>>(Sh, Wqkvh, bqkv, QKVh, MROWS, 3*DMp, DMp, 0, 1);
        unpack_qk<<<elems/256, 256>>>();
        transpose_v<<<dim3(SEQ/32, (HDp + 31)/32, GHEADS), dim3(32, 8)>>>(3*DMp, 2*DMp);
        fused_attn<<<dim3(8, GHEADS), 256, FASMEM>>>();
        gemm_nt_h<<<dim3((DMp + 127)/128, MROWS/128), 256, TCSMEM>>>(ATTh, Woh, bo, O, MROWS, DMp, DMp, 0, 0);
        add_ln<<<MROWS, 256>>>(S, Sh, O, ln1w, ln1b);
        gemm_nt_h<<<dim3(DFFp/128, MROWS/128), 256, TCSMEM>>>(Sh, W1h, b1, FFNh, MROWS, DFFp, DMp, 1, 1);
        gemm_nt_h<<<dim3((DMp + 127)/128, MROWS/128), 256, TCSMEM>>>(FFNh, W2h, b2, O, MROWS, DMp, DFFp, 0, 0);
        add_ln<<<MROWS, 256>>>(S, Sh, O, ln2w, ln2b);
    }

    // ===================== Layer 1: pruned 25-token path =====================
    {
        const __half* wqkvh = Wqkvh + (size_t)1 * 3 * DMp * DMp;
        const float*  bq    = bqkv  + (size_t)1 * 3 * DMp;
        gemm_nt_h<<<dim3((2*DMp + 127)/128, MROWS/128), 256, TCSMEM>>>(Sh, wqkvh + (size_t)DMp*DMp, bq + DMp, QKVh, MROWS, 2*DMp, DMp, 0, 1);
        unpack_k<<<elems/256, 256>>>();
        transpose_v<<<dim3(SEQ/32, (HDp + 31)/32, GHEADS), dim3(32, 8)>>>(2*DMp, DMp);
        gather_S2<<<(M2*DMp + 255)/256, 256>>>();
        gemm_nt_h<<<dim3((DMp + 127)/128, (M2 + 127)/128), 256, TCSMEM>>>(S2h, wqkvh, bq, FFNh, M2, DMp, DMp, 0, 1);
        unpack_q25<<<(M2*DMp + 255)/256, 256>>>();
        gemm_scores25<<<dim3(SEQ/128, GHEADS), 256>>>();
        softmax_rows<<<(GHEADS*25 + 7)/8, 256>>>(GHEADS*25);
        gemm_av25<<<GHEADS*25, 160>>>();
        gemm_nt_h<<<dim3((DMp + 127)/128, (M2 + 127)/128), 256, TCSMEM>>>(ATTh, Woh + (size_t)DMp*DMp, bo + DMp, O2, M2, DMp, DMp, 0, 0);
        add_ln<<<M2, 256>>>(S2, S2h, O2, ln1w + DMp, ln1b + DMp);
        gemm_nt_h<<<dim3(DFFp/128, (M2 + 127)/128), 256, TCSMEM>>>(S2h, W1h + (size_t)DFFp*DMp, b1 + DFFp, FFNh, M2, DFFp, DMp, 1, 1);
        gemm_nt_h<<<dim3((DMp + 127)/128, (M2 + 127)/128), 256, TCSMEM>>>(FFNh, W2h + (size_t)DMp*DFFp, b2 + DMp, O2, M2, DMp, DFFp, 0, 0);
        add_ln<<<M2, 256>>>(S2, S2h, O2, ln2w + DMp, ln2b + DMp);
    }

    gather_out<<<(Bsz*25*1024)/256, 256>>>((float*)d_out);
}

// round 13
// speedup vs baseline: 1.0053x; 1.0053x over previous
#include <cuda_runtime.h>
#include <cuda_fp16.h>
#include <math.h>
#include <stdint.h>

#define Bsz   64
#define Dd    1024
#define DMp   1088
#define Hh    8
#define HDp   136
#define DFFp  2048
#define SEQ   512
#define Rr    487
#define MROWS (Bsz*SEQ)     /* 32768 */
#define GHEADS (Bsz*Hh)     /* 512  */
#define M2    (Bsz*25)      /* 1600 */
#define Ll    2

// ---------------- scratch (device globals) -----------------------------------
__device__ float  g_S  [(size_t)MROWS*DMp];
__device__ __half g_Sh [(size_t)MROWS*DMp];
__device__ __half g_QKVh[(size_t)MROWS*3*DMp];
__device__ __half g_Qh [(size_t)GHEADS*SEQ*HDp];
__device__ __half g_Kh [(size_t)GHEADS*SEQ*HDp];
__device__ __half g_Vth[(size_t)GHEADS*HDp*SEQ];
__device__ __half g_Ph [(size_t)GHEADS*SEQ*SEQ];
__device__ __half g_ATTh[(size_t)MROWS*DMp];
__device__ __half g_FFNh[(size_t)MROWS*DFFp];
__device__ __half g_Oh [(size_t)MROWS*DMp];       // fp16 proj output for add_ln
__device__ float  g_S2 [(size_t)M2*DMp];
__device__ __half g_S2h[(size_t)M2*DMp];
__device__ __half g_O2h[(size_t)M2*DMp];
__device__ float  g_bias[Bsz*SEQ];
__device__ __half g_Wqkvh[(size_t)Ll*3*DMp*DMp];
__device__ __half g_Woh  [(size_t)Ll*DMp*DMp];
__device__ __half g_W1h  [(size_t)Ll*DFFp*DMp];
__device__ __half g_W2h  [(size_t)Ll*DMp*DFFp];

// ---------------- f32 -> f16 convert ------------------------------------------
__global__ void cvt_f2h(const float4* __restrict__ s, __half* __restrict__ d, int n4)
{
    int i = blockIdx.x * blockDim.x + threadIdx.x;
    if (i >= n4) return;
    float4 v = s[i];
    union { __half2 h; uint32_t u; } p0, p1;
    p0.h = __floats2half2_rn(v.x, v.y);
    p1.h = __floats2half2_rn(v.z, v.w);
    *(uint2*)(d + (size_t)i*4) = make_uint2(p0.u, p1.u);
}

// ---------------- build S tensor + mask bias ------------------------------------
__global__ void build_S(const float* __restrict__ q, const float* __restrict__ sa,
                        const float* __restrict__ si, const float* __restrict__ ref,
                        const int* __restrict__ na, const int* __restrict__ ni)
{
    size_t idx = (size_t)blockIdx.x * blockDim.x + threadIdx.x;
    if (idx >= (size_t)MROWS * DMp) return;
    int c = (int)(idx % DMp);
    size_t row = idx / DMp;
    int t = (int)(row % SEQ);
    int b = (int)(row / SEQ);
    float v;
    if (t == 0)       v = (c < Dd) ? q  [(size_t)b*Dd + c]              : 0.f;
    else if (t < 13)  v = (c < Dd) ? sa [((size_t)b*12 + (t-1))*Dd + c] : 1.f;
    else if (t < 25)  v = (c < Dd) ? si [((size_t)b*12 + (t-13))*Dd + c]: -1.f;
    else              v = (c < Dd) ? ref[((size_t)b*Rr + (t-25))*Dd + c]: 0.f;
    g_S[idx]  = v;
    g_Sh[idx] = __float2half_rn(v);
    if (c == 0) {
        int ra = na[b], ri = ni[b];
        bool m = (t == 0)
              || (t >= 1  && t < 13 && t < ra + 1)
              || (t >= 13 && t < 25 && t < ri + 13);
        g_bias[b*SEQ + t] = m ? -1.0e9f : 0.f;
    }
}

// ================= fp16 tensor-core GEMM engine v10 ==========================
// 16-half chunks, NSTG=6 stages, paired-chunk pipeline: one barrier per 2 chunks.
#define SMKH 24
#define NSTG 6
#define TCSMEM (2 * NSTG * 128 * SMKH * 2)   /* 73728 B */

typedef __half TcTile[128][SMKH];

__device__ __forceinline__ uint32_t smem_u32(const void* p) {
    return (uint32_t)__cvta_generic_to_shared(p);
}

// src-size 0 form ZERO-FILLS the 16 bytes (load-bearing for K tails).
__device__ __forceinline__ void cpa16(uint32_t dst, const __half* src, bool pred) {
    int sz = pred ? 16 : 0;
    asm volatile("cp.async.cg.shared.global [%0], [%1], 16, %2;\n"
                 :: "r"(dst), "l"(src), "r"(sz));
}
#define CP_COMMIT() asm volatile("cp.async.commit_group;\n" ::)
#define CP_WAIT(N)  asm volatile("cp.async.wait_group %0;\n" :: "n"(N))

#define LDSM_X4(r0,r1,r2,r3,addr) \
    asm volatile("ldmatrix.sync.aligned.m8n8.x4.shared.b16 {%0,%1,%2,%3}, [%4];" \
                 : "=r"(r0),"=r"(r1),"=r"(r2),"=r"(r3) : "r"(addr))

__device__ __forceinline__ void mma_f16(float (&d)[4], const uint32_t (&a)[4],
                                        const uint32_t (&b)[2]) {
    asm volatile(
        "mma.sync.aligned.m16n8k16.row.col.f32.f16.f16.f32 "
        "{%0,%1,%2,%3}, {%4,%5,%6,%7}, {%8,%9}, {%0,%1,%2,%3};"
        : "+f"(d[0]), "+f"(d[1]), "+f"(d[2]), "+f"(d[3])
        : "r"(a[0]), "r"(a[1]), "r"(a[2]), "r"(a[3]), "r"(b[0]), "r"(b[1]));
}

__device__ __forceinline__ void tc4_step(
    float (&acc)[4][4][4], const TcTile& As, const TcTile& Bs,
    int mb, int nb, int lane)
{
    uint32_t b[4][2];
    {
        int row = nb + ((lane >> 4) << 3) + (lane & 7);
        int kh  = ((lane >> 3) & 1) * 8;
        LDSM_X4(b[0][0], b[0][1], b[1][0], b[1][1], smem_u32(&Bs[row][kh]));
        LDSM_X4(b[2][0], b[2][1], b[3][0], b[3][1], smem_u32(&Bs[row + 16][kh]));
    }
    int arow = (lane & 15);
    int akh  = (lane >> 4) * 8;
    #pragma unroll
    for (int mi = 0; mi < 4; mi++) {
        uint32_t a[4];
        LDSM_X4(a[0], a[1], a[2], a[3], smem_u32(&As[mb + mi*16 + arow][akh]));
        #pragma unroll
        for (int ni = 0; ni < 4; ni++)
            mma_f16(acc[mi][ni], a, b[ni]);
    }
}

__device__ __forceinline__ void tc4_loop_f16(
    const __half* __restrict__ A, const __half* __restrict__ Bw,
    int K, int M, int N, int bm, int bn,
    float (&acc)[4][4][4], TcTile* As, TcTile* Bs, int tid)
{
    int lane = tid & 31, wid = tid >> 5;
    int mb = (wid >> 2) * 64, nb = (wid & 3) * 32;
    int rr = tid >> 1;            // 0..127
    int lch = (tid & 1) * 8;      // 0 or 8 halves

    int ar = bm + rr, br = bn + rr;
    bool av = ar < M, bv = br < N;
    const __half* Aprow = A  + (size_t)(av ? ar : 0) * K + lch;
    const __half* Bprow = Bw + (size_t)(bv ? br : 0) * K + lch;

    int chunks = (K + 15) / 16;        // >= 9 for our shapes
    int npairs = (chunks + 1) / 2;

    // prologue: pairs 0,1 (chunks 0..3), one commit group per pair
    #pragma unroll
    for (int gp = 0; gp < 2; gp++) {
        #pragma unroll
        for (int s = 0; s < 2; s++) {
            int ch = gp*2 + s;
            int k0 = ch * 16;
            cpa16(smem_u32(&As[ch][rr][lch]), Aprow + k0, av && (k0 + lch) < K);
            cpa16(smem_u32(&Bs[ch][rr][lch]), Bprow + k0, bv && (k0 + lch) < K);
        }
        CP_COMMIT();
    }

    int buf = 0;   // even: 0,2,4
    for (int i = 0; i < npairs; i++) {
        CP_WAIT(1);
        __syncthreads();
        // prefetch pair i+2 (zero-filled if beyond K; group always committed)
        {
            int st0 = buf + 4; if (st0 >= NSTG) st0 -= NSTG;
            #pragma unroll
            for (int s = 0; s < 2; s++) {
                int k0 = ((i + 2) * 2 + s) * 16;
                int st = st0 + s;
                cpa16(smem_u32(&As[st][rr][lch]), Aprow + k0, av && (k0 + lch) < K);
                cpa16(smem_u32(&Bs[st][rr][lch]), Bprow + k0, bv && (k0 + lch) < K);
            }
            CP_COMMIT();
        }
        tc4_step(acc, As[buf],     Bs[buf],     mb, nb, lane);
        tc4_step(acc, As[buf + 1], Bs[buf + 1], mb, nb, lane);
        buf += 2; if (buf >= NSTG) buf -= NSTG;
    }
}

// ---------------- generic fp16 GEMM: C = A @ W^T + bias, relu, f32/f16 out ----
__global__ void __launch_bounds__(256, 2)
gemm_nt_h(const __half* __restrict__ A, const __half* __restrict__ Bw,
          const float* __restrict__ bias, void* __restrict__ Cv,
          int M, int N, int K, int relu, int outHalf)
{
    extern __shared__ __align__(16) char dsm[];
    TcTile* As = reinterpret_cast<TcTile*>(dsm);
    TcTile* Bs = reinterpret_cast<TcTile*>(dsm + NSTG * 128 * SMKH * 2);
    int tid = threadIdx.x, lane = tid & 31, wid = tid >> 5;
    int mb = (wid >> 2) * 64, nb = (wid & 3) * 32;
    int gid = lane >> 2, tig = lane & 3;
    int bm = blockIdx.y * 128, bn = blockIdx.x * 128;
    float acc[4][4][4] = {};
    tc4_loop_f16(A, Bw, K, M, N, bm, bn, acc, As, Bs, tid);
    #pragma unroll
    for (int mi = 0; mi < 4; mi++) {
        int row = bm + mb + mi*16 + gid;
        #pragma unroll
        for (int ni = 0; ni < 4; ni++) {
            int col = bn + nb + ni*8 + tig*2;
            if (col >= N) continue;
            float b0 = bias[col], b1 = bias[col+1];
            float v0 = acc[mi][ni][0] + b0, v1 = acc[mi][ni][1] + b1;
            float v2 = acc[mi][ni][2] + b0, v3 = acc[mi][ni][3] + b1;
            if (relu) {
                v0 = fmaxf(v0, 0.f); v1 = fmaxf(v1, 0.f);
                v2 = fmaxf(v2, 0.f); v3 = fmaxf(v3, 0.f);
            }
            if (outHalf) {
                __half* C = (__half*)Cv;
                if (row < M)     *(__half2*)(C + (size_t)row * N + col)       = __floats2half2_rn(v0, v1);
                if (row + 8 < M) *(__half2*)(C + (size_t)(row + 8) * N + col) = __floats2half2_rn(v2, v3);
            } else {
                float* C = (float*)Cv;
                if (row < M)     *(float2*)(C + (size_t)row * N + col)       = make_float2(v0, v1);
                if (row + 8 < M) *(float2*)(C + (size_t)(row + 8) * N + col) = make_float2(v2, v3);
            }
        }
    }
}

// ---------------- layer-1 scores: Ph = f16(scale*Q@K^T + bias) ---------------
__global__ void __launch_bounds__(256, 2) gemm_scores_tc()
{
    extern __shared__ __align__(16) char dsm[];
    TcTile* As = reinterpret_cast<TcTile*>(dsm);
    TcTile* Bs = reinterpret_cast<TcTile*>(dsm + NSTG * 128 * SMKH * 2);
    int g = blockIdx.z, b = g >> 3;
    const __half* A  = g_Qh + (size_t)g * SEQ * HDp;
    const __half* Bw = g_Kh + (size_t)g * SEQ * HDp;
    __half* C = g_Ph + (size_t)g * SEQ * SEQ;
    int tid = threadIdx.x, lane = tid & 31, wid = tid >> 5;
    int mb = (wid >> 2) * 64, nb = (wid & 3) * 32;
    int gid = lane >> 2, tig = lane & 3;
    int bm = blockIdx.y * 128, bn = blockIdx.x * 128;
    float acc[4][4][4] = {};
    tc4_loop_f16(A, Bw, HDp, SEQ, SEQ, bm, bn, acc, As, Bs, tid);
    const float scale = rsqrtf((float)HDp);
    #pragma unroll
    for (int mi = 0; mi < 4; mi++) {
        int row = bm + mb + mi*16 + gid;
        #pragma unroll
        for (int ni = 0; ni < 4; ni++) {
            int col = bn + nb + ni*8 + tig*2;
            float b0 = g_bias[b*SEQ + col], b1 = g_bias[b*SEQ + col + 1];
            *(__half2*)(C + (size_t)row * SEQ + col) =
                __floats2half2_rn(acc[mi][ni][0]*scale + b0, acc[mi][ni][1]*scale + b1);
            *(__half2*)(C + (size_t)(row+8) * SEQ + col) =
                __floats2half2_rn(acc[mi][ni][2]*scale + b0, acc[mi][ni][3]*scale + b1);
        }
    }
}

// ---------------- layer-1 O = P @ V -> fp16 ATTh -------------------------------
__global__ void __launch_bounds__(256, 2) gemm_av_tc()
{
    extern __shared__ __align__(16) char dsm[];
    TcTile* As = reinterpret_cast<TcTile*>(dsm);
    TcTile* Bs = reinterpret_cast<TcTile*>(dsm + NSTG * 128 * SMKH * 2);
    int g = blockIdx.z, b = g >> 3, h = g & 7;
    const __half* A  = g_Ph  + (size_t)g * SEQ * SEQ;
    const __half* Bw = g_Vth + (size_t)g * HDp * SEQ;
    int tid = threadIdx.x, lane = tid & 31, wid = tid >> 5;
    int mb = (wid >> 2) * 64, nb = (wid & 3) * 32;
    int gid = lane >> 2, tig = lane & 3;
    int bm = blockIdx.y * 128, bn = blockIdx.x * 128;
    float acc[4][4][4] = {};
    tc4_loop_f16(A, Bw, SEQ, SEQ, HDp, bm, bn, acc, As, Bs, tid);
    #pragma unroll
    for (int mi = 0; mi < 4; mi++) {
        int row = bm + mb + mi*16 + gid;
        #pragma unroll
        for (int ni = 0; ni < 4; ni++) {
            int col = bn + nb + ni*8 + tig*2;
            if (col >= HDp) continue;
            __half* base = g_ATTh + ((size_t)b*SEQ + row) * DMp + h*HDp + col;
            *(__half2*)(base) = __floats2half2_rn(acc[mi][ni][0], acc[mi][ni][1]);
            *(__half2*)(base + (size_t)8*DMp) = __floats2half2_rn(acc[mi][ni][2], acc[mi][ni][3]);
        }
    }
}

// ---------------- unpack kernels ------------------------------------------------
__global__ void unpack_qk()
{
    size_t idx = (size_t)blockIdx.x * blockDim.x + threadIdx.x;
    if (idx >= (size_t)MROWS * DMp) return;
    int c = (int)(idx % DMp);
    size_t row = idx / DMp;
    int t = (int)(row % SEQ);
    int b = (int)(row / SEQ);
    int h = c / HDp, d = c % HDp;
    const __half* src = g_QKVh + row * (size_t)(3*DMp);
    size_t gh = (size_t)(b*Hh + h);
    g_Qh[(gh*SEQ + t)*HDp + d] = src[c];
    g_Kh[(gh*SEQ + t)*HDp + d] = src[DMp + c];
}

__global__ void unpack_k()
{
    size_t idx = (size_t)blockIdx.x * blockDim.x + threadIdx.x;
    if (idx >= (size_t)MROWS * DMp) return;
    int c = (int)(idx % DMp);
    size_t row = idx / DMp;
    int t = (int)(row % SEQ);
    int b = (int)(row / SEQ);
    int h = c / HDp, d = c % HDp;
    g_Kh[((size_t)(b*Hh + h)*SEQ + t)*HDp + d] = g_QKVh[row * (size_t)(2*DMp) + c];
}

__global__ void transpose_v(int rowW, int colOff)
{
    __shared__ __half tile[32][33];
    int gh = blockIdx.z;
    int b = gh >> 3, h = gh & 7;
    int t0 = blockIdx.x * 32, d0 = blockIdx.y * 32;
    int tx = threadIdx.x, ty = threadIdx.y;
    const __half* src = g_QKVh + (size_t)b * SEQ * rowW + colOff + h * HDp;
    #pragma unroll
    for (int i = 0; i < 4; i++) {
        int t = t0 + ty + i*8;
        int d = d0 + tx;
        if (d < HDp) tile[ty + i*8][tx] = src[(size_t)t * rowW + d];
    }
    __syncthreads();
    #pragma unroll
    for (int i = 0; i < 4; i++) {
        int d = d0 + ty + i*8;
        int t = t0 + tx;
        if (d < HDp) g_Vth[((size_t)gh*HDp + d)*SEQ + t] = tile[tx][ty + i*8];
    }
}

__global__ void gather_S2()
{
    size_t idx = (size_t)blockIdx.x * blockDim.x + threadIdx.x;
    if (idx >= (size_t)M2 * DMp) return;
    int c = (int)(idx % DMp);
    int i = (int)(idx / DMp);
    int t = i % 25, b = i / 25;
    float v = g_S[((size_t)b*SEQ + t)*DMp + c];
    g_S2[idx]  = v;
    g_S2h[idx] = __float2half_rn(v);
}

__global__ void unpack_q25()
{
    size_t idx = (size_t)blockIdx.x * blockDim.x + threadIdx.x;
    if (idx >= (size_t)M2 * DMp) return;
    int c = (int)(idx % DMp);
    int i = (int)(idx / DMp);
    int t = i % 25, b = i / 25;
    int h = c / HDp, d = c % HDp;
    int g = b*Hh + h;
    g_Qh[((size_t)g*25 + t)*HDp + d] = g_FFNh[(size_t)i*DMp + c];
}

__device__ __forceinline__ float4 ldh4(const __half* p) {
    uint2 u = *(const uint2*)p;
    float2 f0 = __half22float2(*(__half2*)&u.x), f1 = __half22float2(*(__half2*)&u.y);
    return make_float4(f0.x, f0.y, f1.x, f1.y);
}

// ---------------- layer-2 compact scores --------------------------------------
__global__ void __launch_bounds__(256) gemm_scores25()
{
    __shared__ float Qs[8][32];
    __shared__ float Ks[8][128];
    int g = blockIdx.y, b = g >> 3;
    int bn = blockIdx.x * 128;
    int tid = threadIdx.x;
    int lr = tid >> 1, lc = (tid & 1) * 4;
    int col = tid & 127, rg = tid >> 7;
    float acc[13];
    #pragma unroll
    for (int i = 0; i < 13; i++) acc[i] = 0.f;
    for (int k0 = 0; k0 < HDp; k0 += 8) {
        float4 kv = ldh4(g_Kh + ((size_t)g*SEQ + bn + lr)*HDp + k0 + lc);
        Ks[lc+0][lr]=kv.x; Ks[lc+1][lr]=kv.y; Ks[lc+2][lr]=kv.z; Ks[lc+3][lr]=kv.w;
        if (tid < 50) {
            int qr = tid >> 1;
            float4 qv = ldh4(g_Qh + ((size_t)g*25 + qr)*HDp + k0 + lc);
            Qs[lc+0][qr]=qv.x; Qs[lc+1][qr]=qv.y; Qs[lc+2][qr]=qv.z; Qs[lc+3][qr]=qv.w;
        }
        __syncthreads();
        #pragma unroll
        for (int kk = 0; kk < 8; kk++) {
            float bvv = Ks[kk][col];
            #pragma unroll
            for (int i = 0; i < 13; i++) {
                int r = rg + 2*i;
                if (r < 25) acc[i] = fmaf(Qs[kk][r], bvv, acc[i]);
            }
        }
        __syncthreads();
    }
    const float scale = rsqrtf((float)HDp);
    float bias = g_bias[b*SEQ + bn + col];
    #pragma unroll
    for (int i = 0; i < 13; i++) {
        int r = rg + 2*i;
        if (r < 25)
            g_Ph[((size_t)g*25 + r)*SEQ + bn + col] = __float2half_rn(acc[i]*scale + bias);
    }
}

// ---------------- warp-per-row softmax over g_Ph -------------------------------
__global__ void softmax_rows(int nrows)
{
    int row = blockIdx.x * 8 + (threadIdx.x >> 5);
    if (row >= nrows) return;
    int lane = threadIdx.x & 31;
    __half* p = g_Ph + (size_t)row * SEQ + lane * 16;
    uint4 u0 = *(const uint4*)(p);
    uint4 u1 = *(const uint4*)(p + 8);
    float v[16];
    {
        const uint32_t* w0 = (const uint32_t*)&u0;
        const uint32_t* w1 = (const uint32_t*)&u1;
        #pragma unroll
        for (int i = 0; i < 4; i++) {
            float2 a = __half22float2(*(const __half2*)&w0[i]);
            float2 b = __half22float2(*(const __half2*)&w1[i]);
            v[2*i]   = a.x; v[2*i+1]   = a.y;
            v[8+2*i] = b.x; v[8+2*i+1] = b.y;
        }
    }
    float m = v[0];
    #pragma unroll
    for (int i = 1; i < 16; i++) m = fmaxf(m, v[i]);
    #pragma unroll
    for (int off = 16; off > 0; off >>= 1)
        m = fmaxf(m, __shfl_xor_sync(0xffffffffu, m, off));
    float s = 0.f;
    #pragma unroll
    for (int i = 0; i < 16; i++) { v[i] = expf(v[i] - m); s += v[i]; }
    #pragma unroll
    for (int off = 16; off > 0; off >>= 1)
        s += __shfl_xor_sync(0xffffffffu, s, off);
    float inv = 1.f / s;
    uint4 o0, o1;
    {
        uint32_t* w0 = (uint32_t*)&o0;
        uint32_t* w1 = (uint32_t*)&o1;
        #pragma unroll
        for (int i = 0; i < 4; i++) {
            __half2 a = __floats2half2_rn(v[2*i]*inv,   v[2*i+1]*inv);
            __half2 b = __floats2half2_rn(v[8+2*i]*inv, v[8+2*i+1]*inv);
            w0[i] = *(uint32_t*)&a;
            w1[i] = *(uint32_t*)&b;
        }
    }
    *(uint4*)(p)     = o0;
    *(uint4*)(p + 8) = o1;
}

// ---------------- layer-2 compact O = P @ V -------------------------------------
__global__ void __launch_bounds__(160) gemm_av25()
{
    int blk = blockIdx.x;
    int g = blk / 25, r = blk % 25;
    int b = g >> 3, h = g & 7;
    __shared__ float Ps[512];
    const __half* prow = g_Ph + ((size_t)g*25 + r)*SEQ;
    int tid = threadIdx.x;
    for (int i = tid; i < SEQ; i += 160) Ps[i] = __half2float(prow[i]);
    __syncthreads();
    if (tid < HDp) {
        const __half* v = g_Vth + ((size_t)g*HDp + tid)*SEQ;
        float s = 0.f;
        #pragma unroll 4
        for (int t = 0; t < SEQ; t += 8) {
            uint4 u = *(const uint4*)(v + t);
            float2 f0 = __half22float2(*(__half2*)&u.x);
            float2 f1 = __half22float2(*(__half2*)&u.y);
            float2 f2 = __half22float2(*(__half2*)&u.z);
            float2 f3 = __half22float2(*(__half2*)&u.w);
            s = fmaf(Ps[t],   f0.x, s); s = fmaf(Ps[t+1], f0.y, s);
            s = fmaf(Ps[t+2], f1.x, s); s = fmaf(Ps[t+3], f1.y, s);
            s = fmaf(Ps[t+4], f2.x, s); s = fmaf(Ps[t+5], f2.y, s);
            s = fmaf(Ps[t+6], f3.x, s); s = fmaf(Ps[t+7], f3.y, s);
        }
        g_ATTh[((size_t)b*25 + r)*DMp + h*HDp + tid] = __float2half_rn(s);
    }
}

// ---------------- residual add + layernorm (o is fp16) --------------------------
__global__ void add_ln(float* __restrict__ x, __half* __restrict__ xh,
                       const __half* __restrict__ o,
                       const float* __restrict__ w, const float* __restrict__ bb)
{
    size_t row = blockIdx.x;
    float* xr = x + row * DMp;
    __half* xhr = xh + row * DMp;
    const __half* orow = o + row * DMp;
    int tid = threadIdx.x;
    float vals[5];
    int cnt = 0;
    float s = 0.f;
    for (int i = tid; i < DMp; i += 256) {
        float v = xr[i] + __half2float(orow[i]);
        vals[cnt++] = v; s += v;
    }
    __shared__ float red[256];
    red[tid] = s; __syncthreads();
    for (int st = 128; st > 0; st >>= 1) { if (tid < st) red[tid] += red[tid + st]; __syncthreads(); }
    float mu = red[0] * (1.f / DMp);
    __syncthreads();
    float s2 = 0.f;
    for (int k = 0; k < cnt; k++) { float d = vals[k] - mu; s2 += d * d; }
    red[tid] = s2; __syncthreads();
    for (int st = 128; st > 0; st >>= 1) { if (tid < st) red[tid] += red[tid + st]; __syncthreads(); }
    float rstd = rsqrtf(red[0] * (1.f / DMp) + 1e-5f);
    int k = 0;
    for (int i = tid; i < DMp; i += 256, k++) {
        float r = (vals[k] - mu) * rstd * w[i] + bb[i];
        xr[i] = r;
        xhr[i] = __float2half_rn(r);
    }
}

// ---------------- gather outputs --------------------------------------------------
__global__ void gather_out(float* __restrict__ out)
{
    size_t idx = (size_t)blockIdx.x * blockDim.x + threadIdx.x;
    if (idx >= (size_t)Bsz * 25 * 1024) return;
    int c = (int)(idx % 1024);
    int rem = (int)(idx / 1024);
    int t = rem % 25;
    int b = rem / 25;
    float v = g_S2[((size_t)b*25 + t) * DMp + c];
    size_t o;
    if (t == 0)      o = (size_t)b * 1024 + c;
    else if (t < 13) o = (size_t)Bsz*1024 + ((size_t)b*12 + (t-1))*1024 + c;
    else             o = (size_t)Bsz*1024 + (size_t)Bsz*12*1024
                       + ((size_t)b*12 + (t-13))*1024 + c;
    out[o] = v;
}

// ---------------- launch ----------------------------------------------------------
extern "C" void kernel_launch(void* const* d_in, const int* in_sizes, int n_in,
                              void* d_out, int out_size)
{
    (void)in_sizes; (void)n_in; (void)out_size;
    const float* q    = (const float*)d_in[0];
    const float* sa   = (const float*)d_in[1];
    const float* si   = (const float*)d_in[2];
    const int*   na   = (const int*)  d_in[3];
    const int*   ni   = (const int*)  d_in[4];
    const float* ref  = (const float*)d_in[5];
    const float* Wqkv = (const float*)d_in[6];
    const float* bqkv = (const float*)d_in[7];
    const float* Wo   = (const float*)d_in[8];
    const float* bo   = (const float*)d_in[9];
    const float* ln1w = (const float*)d_in[10];
    const float* ln1b = (const float*)d_in[11];
    const float* W1   = (const float*)d_in[12];
    const float* b1   = (const float*)d_in[13];
    const float* W2   = (const float*)d_in[14];
    const float* b2   = (const float*)d_in[15];
    const float* ln2w = (const float*)d_in[16];
    const float* ln2b = (const float*)d_in[17];

    float *S, *S2;
    __half *Sh, *QKVh, *ATTh, *FFNh, *Oh, *S2h, *O2h, *Wqkvh, *Woh, *W1h, *W2h;
    cudaGetSymbolAddress((void**)&S,    g_S);
    cudaGetSymbolAddress((void**)&Sh,   g_Sh);
    cudaGetSymbolAddress((void**)&QKVh, g_QKVh);
    cudaGetSymbolAddress((void**)&ATTh, g_ATTh);
    cudaGetSymbolAddress((void**)&FFNh, g_FFNh);
    cudaGetSymbolAddress((void**)&Oh,   g_Oh);
    cudaGetSymbolAddress((void**)&S2,   g_S2);
    cudaGetSymbolAddress((void**)&S2h,  g_S2h);
    cudaGetSymbolAddress((void**)&O2h,  g_O2h);
    cudaGetSymbolAddress((void**)&Wqkvh, g_Wqkvh);
    cudaGetSymbolAddress((void**)&Woh,   g_Woh);
    cudaGetSymbolAddress((void**)&W1h,   g_W1h);
    cudaGetSymbolAddress((void**)&W2h,   g_W2h);

    cudaFuncSetAttribute(gemm_nt_h,      cudaFuncAttributeMaxDynamicSharedMemorySize, TCSMEM);
    cudaFuncSetAttribute(gemm_scores_tc, cudaFuncAttributeMaxDynamicSharedMemorySize, TCSMEM);
    cudaFuncSetAttribute(gemm_av_tc,     cudaFuncAttributeMaxDynamicSharedMemorySize, TCSMEM);

    // weight conversion (f32 -> f16)
    {
        int n;
        n = Ll*3*DMp*DMp/4; cvt_f2h<<<(n+255)/256, 256>>>((const float4*)Wqkv, Wqkvh, n);
        n = Ll*DMp*DMp/4;   cvt_f2h<<<(n+255)/256, 256>>>((const float4*)Wo,   Woh,   n);
        n = Ll*DFFp*DMp/4;  cvt_f2h<<<(n+255)/256, 256>>>((const float4*)W1,   W1h,   n);
        n = Ll*DMp*DFFp/4;  cvt_f2h<<<(n+255)/256, 256>>>((const float4*)W2,   W2h,   n);
    }

    const int elems = MROWS * DMp;
    build_S<<<elems/256, 256>>>(q, sa, si, ref, na, ni);

    // ===================== Layer 0: full 512-token path =====================
    {
        gemm_nt_h<<<dim3((3*DMp + 127)/128, MROWS/128), 256, TCSMEM>>>(Sh, Wqkvh, bqkv, QKVh, MROWS, 3*DMp, DMp, 0, 1);
        unpack_qk<<<elems/256, 256>>>();
        transpose_v<<<dim3(SEQ/32, (HDp + 31)/32, GHEADS), dim3(32, 8)>>>(3*DMp, 2*DMp);
        gemm_scores_tc<<<dim3(SEQ/128, SEQ/128, GHEADS), 256, TCSMEM>>>();
        softmax_rows<<<(GHEADS*SEQ + 7)/8, 256>>>(GHEADS*SEQ);
        gemm_av_tc<<<dim3((HDp + 127)/128, SEQ/128, GHEADS), 256, TCSMEM>>>();
        gemm_nt_h<<<dim3((DMp + 127)/128, MROWS/128), 256, TCSMEM>>>(ATTh, Woh, bo, Oh, MROWS, DMp, DMp, 0, 1);
        add_ln<<<MROWS, 256>>>(S, Sh, Oh, ln1w, ln1b);
        gemm_nt_h<<<dim3(DFFp/128, MROWS/128), 256, TCSMEM>>>(Sh, W1h, b1, FFNh, MROWS, DFFp, DMp, 1, 1);
        gemm_nt_h<<<dim3((DMp + 127)/128, MROWS/128), 256, TCSMEM>>>(FFNh, W2h, b2, Oh, MROWS, DMp, DFFp, 0, 1);
        add_ln<<<MROWS, 256>>>(S, Sh, Oh, ln2w, ln2b);
    }

    // ===================== Layer 1: pruned 25-token path =====================
    {
        const __half* wqkvh = Wqkvh + (size_t)1 * 3 * DMp * DMp;
        const float*  bq    = bqkv  + (size_t)1 * 3 * DMp;
        gemm_nt_h<<<dim3((2*DMp + 127)/128, MROWS/128), 256, TCSMEM>>>(Sh, wqkvh + (size_t)DMp*DMp, bq + DMp, QKVh, MROWS, 2*DMp, DMp, 0, 1);
        unpack_k<<<elems/256, 256>>>();
        transpose_v<<<dim3(SEQ/32, (HDp + 31)/32, GHEADS), dim3(32, 8)>>>(2*DMp, DMp);
        gather_S2<<<(M2*DMp + 255)/256, 256>>>();
        gemm_nt_h<<<dim3((DMp + 127)/128, (M2 + 127)/128), 256, TCSMEM>>>(S2h, wqkvh, bq, FFNh, M2, DMp, DMp, 0, 1);
        unpack_q25<<<(M2*DMp + 255)/256, 256>>>();
        gemm_scores25<<<dim3(SEQ/128, GHEADS), 256>>>();
        softmax_rows<<<(GHEADS*25 + 7)/8, 256>>>(GHEADS*25);
        gemm_av25<<<GHEADS*25, 160>>>();
        gemm_nt_h<<<dim3((DMp + 127)/128, (M2 + 127)/128), 256, TCSMEM>>>(ATTh, Woh + (size_t)DMp*DMp, bo + DMp, O2h, M2, DMp, DMp, 0, 1);
        add_ln<<<M2, 256>>>(S2, S2h, O2h, ln1w + DMp, ln1b + DMp);
        gemm_nt_h<<<dim3(DFFp/128, (M2 + 127)/128), 256, TCSMEM>>>(S2h, W1h + (size_t)DFFp*DMp, b1 + DFFp, FFNh, M2, DFFp, DMp, 1, 1);
        gemm_nt_h<<<dim3((DMp + 127)/128, (M2 + 127)/128), 256, TCSMEM>>>(FFNh, W2h + (size_t)DMp*DFFp, b2 + DMp, O2h, M2, DMp, DFFp, 0, 1);
        add_ln<<<M2, 256>>>(S2, S2h, O2h, ln2w + DMp, ln2b + DMp);
    }

    gather_out<<<(Bsz*25*1024)/256, 256>>>((float*)d_out);
}

// round 15
// speedup vs baseline: 1.0461x; 1.0406x over previous
#include <cuda_runtime.h>
#include <cuda_fp16.h>
#include <math.h>
#include <stdint.h>

#define Bsz   64
#define Dd    1024
#define DMp   1088
#define Hh    8
#define HDp   136
#define DFFp  2048
#define SEQ   512
#define Rr    487
#define MROWS (Bsz*SEQ)     /* 32768 */
#define GHEADS (Bsz*Hh)     /* 512  */
#define M2    (Bsz*25)      /* 1600 */
#define Ll    2

// ---------------- scratch (device globals) -----------------------------------
__device__ float  g_S  [(size_t)MROWS*DMp];
__device__ __half g_Sh [(size_t)MROWS*DMp];
__device__ __half g_QKVh[(size_t)MROWS*3*DMp];
__device__ __half g_Qh [(size_t)GHEADS*SEQ*HDp];
__device__ __half g_Kh [(size_t)GHEADS*SEQ*HDp];
__device__ __half g_Vth[(size_t)GHEADS*HDp*SEQ];
__device__ __half g_Ph [(size_t)GHEADS*SEQ*SEQ];
__device__ __half g_ATTh[(size_t)MROWS*DMp];
__device__ __half g_FFNh[(size_t)MROWS*DFFp];
__device__ float  g_O  [(size_t)MROWS*DMp];
__device__ float  g_S2 [(size_t)M2*DMp];
__device__ __half g_S2h[(size_t)M2*DMp];
__device__ float  g_O2 [(size_t)M2*DMp];
__device__ float  g_bias[Bsz*SEQ];
__device__ __half g_Wqkvh[(size_t)Ll*3*DMp*DMp];
__device__ __half g_Woh  [(size_t)Ll*DMp*DMp];
__device__ __half g_W1h  [(size_t)Ll*DFFp*DMp];
__device__ __half g_W2h  [(size_t)Ll*DMp*DFFp];

// epilogue modes
#define MODE_DENSE_H 0
#define MODE_DENSE_F 1
#define MODE_QKV1    2   /* N=3*DMp: Q,K scatter per-head; V packed into Cv (QKVh, rowW 3*DMp) */
#define MODE_KV2     3   /* N=2*DMp: K scatter per-head; V packed into Cv (QKVh, rowW 2*DMp) */
#define MODE_Q25     4   /* N=DMp, M=M2: Q scatter to compact per-head (stride 25) */

// ---------------- f32 -> f16 convert ------------------------------------------
__global__ void cvt_f2h(const float4* __restrict__ s, __half* __restrict__ d, int n4)
{
    int i = blockIdx.x * blockDim.x + threadIdx.x;
    if (i >= n4) return;
    float4 v = s[i];
    union { __half2 h; uint32_t u; } p0, p1;
    p0.h = __floats2half2_rn(v.x, v.y);
    p1.h = __floats2half2_rn(v.z, v.w);
    *(uint2*)(d + (size_t)i*4) = make_uint2(p0.u, p1.u);
}

// ---------------- build S tensor + mask bias ------------------------------------
__global__ void build_S(const float* __restrict__ q, const float* __restrict__ sa,
                        const float* __restrict__ si, const float* __restrict__ ref,
                        const int* __restrict__ na, const int* __restrict__ ni)
{
    size_t idx = (size_t)blockIdx.x * blockDim.x + threadIdx.x;
    if (idx >= (size_t)MROWS * DMp) return;
    int c = (int)(idx % DMp);
    size_t row = idx / DMp;
    int t = (int)(row % SEQ);
    int b = (int)(row / SEQ);
    float v;
    if (t == 0)       v = (c < Dd) ? q  [(size_t)b*Dd + c]              : 0.f;
    else if (t < 13)  v = (c < Dd) ? sa [((size_t)b*12 + (t-1))*Dd + c] : 1.f;
    else if (t < 25)  v = (c < Dd) ? si [((size_t)b*12 + (t-13))*Dd + c]: -1.f;
    else              v = (c < Dd) ? ref[((size_t)b*Rr + (t-25))*Dd + c]: 0.f;
    g_S[idx]  = v;
    g_Sh[idx] = __float2half_rn(v);
    if (c == 0) {
        int ra = na[b], ri = ni[b];
        bool m = (t == 0)
              || (t >= 1  && t < 13 && t < ra + 1)
              || (t >= 13 && t < 25 && t < ri + 13);
        g_bias[b*SEQ + t] = m ? -1.0e9f : 0.f;
    }
}

// ================= fp16 tensor-core GEMM engine (R11 proven) =================
#define SMKH 24
#define NSTG 4
#define TCSMEM (2 * NSTG * 128 * SMKH * 2)   /* 49152 B */

typedef __half TcTile[128][SMKH];

__device__ __forceinline__ uint32_t smem_u32(const void* p) {
    return (uint32_t)__cvta_generic_to_shared(p);
}

__device__ __forceinline__ void cpa16(uint32_t dst, const __half* src, bool pred) {
    int sz = pred ? 16 : 0;
    asm volatile("cp.async.cg.shared.global [%0], [%1], 16, %2;\n"
                 :: "r"(dst), "l"(src), "r"(sz));
}
#define CP_COMMIT() asm volatile("cp.async.commit_group;\n" ::)
#define CP_WAIT(N)  asm volatile("cp.async.wait_group %0;\n" :: "n"(N))

#define LDSM_X4(r0,r1,r2,r3,addr) \
    asm volatile("ldmatrix.sync.aligned.m8n8.x4.shared.b16 {%0,%1,%2,%3}, [%4];" \
                 : "=r"(r0),"=r"(r1),"=r"(r2),"=r"(r3) : "r"(addr))

__device__ __forceinline__ void mma_f16(float (&d)[4], const uint32_t (&a)[4],
                                        const uint32_t (&b)[2]) {
    asm volatile(
        "mma.sync.aligned.m16n8k16.row.col.f32.f16.f16.f32 "
        "{%0,%1,%2,%3}, {%4,%5,%6,%7}, {%8,%9}, {%0,%1,%2,%3};"
        : "+f"(d[0]), "+f"(d[1]), "+f"(d[2]), "+f"(d[3])
        : "r"(a[0]), "r"(a[1]), "r"(a[2]), "r"(a[3]), "r"(b[0]), "r"(b[1]));
}

__device__ __forceinline__ void tc4_step(
    float (&acc)[4][4][4], const TcTile& As, const TcTile& Bs,
    int mb, int nb, int lane)
{
    uint32_t b[4][2];
    {
        int row = nb + ((lane >> 4) << 3) + (lane & 7);
        int kh  = ((lane >> 3) & 1) * 8;
        LDSM_X4(b[0][0], b[0][1], b[1][0], b[1][1], smem_u32(&Bs[row][kh]));
        LDSM_X4(b[2][0], b[2][1], b[3][0], b[3][1], smem_u32(&Bs[row + 16][kh]));
    }
    int arow = (lane & 15);
    int akh  = (lane >> 4) * 8;
    #pragma unroll
    for (int mi = 0; mi < 4; mi++) {
        uint32_t a[4];
        LDSM_X4(a[0], a[1], a[2], a[3], smem_u32(&As[mb + mi*16 + arow][akh]));
        #pragma unroll
        for (int ni = 0; ni < 4; ni++)
            mma_f16(acc[mi][ni], a, b[ni]);
    }
}

__device__ __forceinline__ void tc4_loop_f16(
    const __half* __restrict__ A, const __half* __restrict__ Bw,
    int K, int M, int N, int bm, int bn,
    float (&acc)[4][4][4], TcTile* As, TcTile* Bs, int tid)
{
    int lane = tid & 31, wid = tid >> 5;
    int mb = (wid >> 2) * 64, nb = (wid & 3) * 32;
    int rr = tid >> 1;
    int lch = (tid & 1) * 8;

    int ar = bm + rr, br = bn + rr;
    bool av = ar < M, bv = br < N;
    const __half* Aprow = A  + (size_t)(av ? ar : 0) * K + lch;
    const __half* Bprow = Bw + (size_t)(bv ? br : 0) * K + lch;

    int chunks = (K + 15) / 16;

    #pragma unroll
    for (int s = 0; s < 3; s++) {
        int k0 = s * 16;
        bool kok = (k0 + lch) < K;
        cpa16(smem_u32(&As[s][rr][lch]), Aprow + k0, kok && av);
        cpa16(smem_u32(&Bs[s][rr][lch]), Bprow + k0, kok && bv);
        CP_COMMIT();
    }

    int buf = 0;
    for (int c = 0; c < chunks; c++) {
        if (c + 1 >= chunks)      { CP_WAIT(0); }
        else if (c + 2 >= chunks) { CP_WAIT(1); }
        else                      { CP_WAIT(2); }
        __syncthreads();
        int kn = (c + 3) * 16;
        if (kn < K) {
            bool kok = (kn + lch) < K;
            int nbuf = (buf + 3) & 3;
            cpa16(smem_u32(&As[nbuf][rr][lch]), Aprow + kn, kok && av);
            cpa16(smem_u32(&Bs[nbuf][rr][lch]), Bprow + kn, kok && bv);
            CP_COMMIT();
        }
        tc4_step(acc, As[buf], Bs[buf], mb, nb, lane);
        buf = (buf + 1) & 3;
    }
}

// ---------------- scatter store helper for fused unpack -------------------------
__device__ __forceinline__ void scatter_store(int mode, int row, int col,
                                              __half2 val, __half* Cv)
{
    int t, b;
    if (mode == MODE_Q25) { t = row % 25; b = row / 25; }
    else                  { t = row & (SEQ - 1); b = row >> 9; }
    if (mode == MODE_QKV1) {
        if (col < DMp) {
            int h = col / HDp, d = col - h * HDp;
            *(__half2*)(g_Qh + ((size_t)(b*Hh + h)*SEQ + t)*HDp + d) = val;
        } else if (col < 2*DMp) {
            int c = col - DMp;
            int h = c / HDp, d = c - h * HDp;
            *(__half2*)(g_Kh + ((size_t)(b*Hh + h)*SEQ + t)*HDp + d) = val;
        } else {
            *(__half2*)(Cv + (size_t)row * (3*DMp) + col) = val;
        }
    } else if (mode == MODE_KV2) {
        if (col < DMp) {
            int h = col / HDp, d = col - h * HDp;
            *(__half2*)(g_Kh + ((size_t)(b*Hh + h)*SEQ + t)*HDp + d) = val;
        } else {
            *(__half2*)(Cv + (size_t)row * (2*DMp) + col) = val;
        }
    } else {  // MODE_Q25
        int h = col / HDp, d = col - h * HDp;
        *(__half2*)(g_Qh + ((size_t)(b*Hh + h)*25 + t)*HDp + d) = val;
    }
}

// ---------------- generic fp16 GEMM with fused-scatter epilogue -----------------
__global__ void __launch_bounds__(256, 2)
gemm_nt_h(const __half* __restrict__ A, const __half* __restrict__ Bw,
          const float* __restrict__ bias, void* __restrict__ Cv,
          int M, int N, int K, int relu, int mode)
{
    extern __shared__ __align__(16) char dsm[];
    TcTile* As = reinterpret_cast<TcTile*>(dsm);
    TcTile* Bs = reinterpret_cast<TcTile*>(dsm + NSTG * 128 * SMKH * 2);
    int tid = threadIdx.x, lane = tid & 31, wid = tid >> 5;
    int mb = (wid >> 2) * 64, nb = (wid & 3) * 32;
    int gid = lane >> 2, tig = lane & 3;
    int bm = blockIdx.y * 128, bn = blockIdx.x * 128;
    float acc[4][4][4] = {};
    tc4_loop_f16(A, Bw, K, M, N, bm, bn, acc, As, Bs, tid);
    #pragma unroll
    for (int mi = 0; mi < 4; mi++) {
        int row = bm + mb + mi*16 + gid;
        #pragma unroll
        for (int ni = 0; ni < 4; ni++) {
            int col = bn + nb + ni*8 + tig*2;
            if (col >= N) continue;
            float b0 = bias[col], b1 = bias[col+1];
            float v0 = acc[mi][ni][0] + b0, v1 = acc[mi][ni][1] + b1;
            float v2 = acc[mi][ni][2] + b0, v3 = acc[mi][ni][3] + b1;
            if (relu) {
                v0 = fmaxf(v0, 0.f); v1 = fmaxf(v1, 0.f);
                v2 = fmaxf(v2, 0.f); v3 = fmaxf(v3, 0.f);
            }
            if (mode == MODE_DENSE_H) {
                __half* C = (__half*)Cv;
                if (row < M)     *(__half2*)(C + (size_t)row * N + col)       = __floats2half2_rn(v0, v1);
                if (row + 8 < M) *(__half2*)(C + (size_t)(row + 8) * N + col) = __floats2half2_rn(v2, v3);
            } else if (mode == MODE_DENSE_F) {
                float* C = (float*)Cv;
                if (row < M)     *(float2*)(C + (size_t)row * N + col)       = make_float2(v0, v1);
                if (row + 8 < M) *(float2*)(C + (size_t)(row + 8) * N + col) = make_float2(v2, v3);
            } else {
                if (row < M)     scatter_store(mode, row,     col, __floats2half2_rn(v0, v1), (__half*)Cv);
                if (row + 8 < M) scatter_store(mode, row + 8, col, __floats2half2_rn(v2, v3), (__half*)Cv);
            }
        }
    }
}

// ---------------- layer-1 scores: Ph = f16(scale*Q@K^T + bias) ---------------
__global__ void __launch_bounds__(256, 2) gemm_scores_tc()
{
    extern __shared__ __align__(16) char dsm[];
    TcTile* As = reinterpret_cast<TcTile*>(dsm);
    TcTile* Bs = reinterpret_cast<TcTile*>(dsm + NSTG * 128 * SMKH * 2);
    int g = blockIdx.z, b = g >> 3;
    const __half* A  = g_Qh + (size_t)g * SEQ * HDp;
    const __half* Bw = g_Kh + (size_t)g * SEQ * HDp;
    __half* C = g_Ph + (size_t)g * SEQ * SEQ;
    int tid = threadIdx.x, lane = tid & 31, wid = tid >> 5;
    int mb = (wid >> 2) * 64, nb = (wid & 3) * 32;
    int gid = lane >> 2, tig = lane & 3;
    int bm = blockIdx.y * 128, bn = blockIdx.x * 128;
    float acc[4][4][4] = {};
    tc4_loop_f16(A, Bw, HDp, SEQ, SEQ, bm, bn, acc, As, Bs, tid);
    const float scale = rsqrtf((float)HDp);
    #pragma unroll
    for (int mi = 0; mi < 4; mi++) {
        int row = bm + mb + mi*16 + gid;
        #pragma unroll
        for (int ni = 0; ni < 4; ni++) {
            int col = bn + nb + ni*8 + tig*2;
            float b0 = g_bias[b*SEQ + col], b1 = g_bias[b*SEQ + col + 1];
            *(__half2*)(C + (size_t)row * SEQ + col) =
                __floats2half2_rn(acc[mi][ni][0]*scale + b0, acc[mi][ni][1]*scale + b1);
            *(__half2*)(C + (size_t)(row+8) * SEQ + col) =
                __floats2half2_rn(acc[mi][ni][2]*scale + b0, acc[mi][ni][3]*scale + b1);
        }
    }
}

// ---------------- layer-1 O = P @ V -> fp16 ATTh -------------------------------
__global__ void __launch_bounds__(256, 2) gemm_av_tc()
{
    extern __shared__ __align__(16) char dsm[];
    TcTile* As = reinterpret_cast<TcTile*>(dsm);
    TcTile* Bs = reinterpret_cast<TcTile*>(dsm + NSTG * 128 * SMKH * 2);
    int g = blockIdx.z, b = g >> 3, h = g & 7;
    const __half* A  = g_Ph  + (size_t)g * SEQ * SEQ;
    const __half* Bw = g_Vth + (size_t)g * HDp * SEQ;
    int tid = threadIdx.x, lane = tid & 31, wid = tid >> 5;
    int mb = (wid >> 2) * 64, nb = (wid & 3) * 32;
    int gid = lane >> 2, tig = lane & 3;
    int bm = blockIdx.y * 128, bn = blockIdx.x * 128;
    float acc[4][4][4] = {};
    tc4_loop_f16(A, Bw, SEQ, SEQ, HDp, bm, bn, acc, As, Bs, tid);
    #pragma unroll
    for (int mi = 0; mi < 4; mi++) {
        int row = bm + mb + mi*16 + gid;
        #pragma unroll
        for (int ni = 0; ni < 4; ni++) {
            int col = bn + nb + ni*8 + tig*2;
            if (col >= HDp) continue;
            __half* base = g_ATTh + ((size_t)b*SEQ + row) * DMp + h*HDp + col;
            *(__half2*)(base) = __floats2half2_rn(acc[mi][ni][0], acc[mi][ni][1]);
            *(__half2*)(base + (size_t)8*DMp) = __floats2half2_rn(acc[mi][ni][2], acc[mi][ni][3]);
        }
    }
}

// ---------------- coalesced V transpose ----------------------------------------
__global__ void transpose_v(int rowW, int colOff)
{
    __shared__ __half tile[32][33];
    int gh = blockIdx.z;
    int b = gh >> 3, h = gh & 7;
    int t0 = blockIdx.x * 32, d0 = blockIdx.y * 32;
    int tx = threadIdx.x, ty = threadIdx.y;
    const __half* src = g_QKVh + (size_t)b * SEQ * rowW + colOff + h * HDp;
    #pragma unroll
    for (int i = 0; i < 4; i++) {
        int t = t0 + ty + i*8;
        int d = d0 + tx;
        if (d < HDp) tile[ty + i*8][tx] = src[(size_t)t * rowW + d];
    }
    __syncthreads();
    #pragma unroll
    for (int i = 0; i < 4; i++) {
        int d = d0 + ty + i*8;
        int t = t0 + tx;
        if (d < HDp) g_Vth[((size_t)gh*HDp + d)*SEQ + t] = tile[tx][ty + i*8];
    }
}

__global__ void gather_S2()
{
    size_t idx = (size_t)blockIdx.x * blockDim.x + threadIdx.x;
    if (idx >= (size_t)M2 * DMp) return;
    int c = (int)(idx % DMp);
    int i = (int)(idx / DMp);
    int t = i % 25, b = i / 25;
    float v = g_S[((size_t)b*SEQ + t)*DMp + c];
    g_S2[idx]  = v;
    g_S2h[idx] = __float2half_rn(v);
}

__device__ __forceinline__ float4 ldh4(const __half* p) {
    uint2 u = *(const uint2*)p;
    float2 f0 = __half22float2(*(__half2*)&u.x), f1 = __half22float2(*(__half2*)&u.y);
    return make_float4(f0.x, f0.y, f1.x, f1.y);
}

// ---------------- layer-2 compact scores --------------------------------------
__global__ void __launch_bounds__(256) gemm_scores25()
{
    __shared__ float Qs[8][32];
    __shared__ float Ks[8][128];
    int g = blockIdx.y, b = g >> 3;
    int bn = blockIdx.x * 128;
    int tid = threadIdx.x;
    int lr = tid >> 1, lc = (tid & 1) * 4;
    int col = tid & 127, rg = tid >> 7;
    float acc[13];
    #pragma unroll
    for (int i = 0; i < 13; i++) acc[i] = 0.f;
    for (int k0 = 0; k0 < HDp; k0 += 8) {
        float4 kv = ldh4(g_Kh + ((size_t)g*SEQ + bn + lr)*HDp + k0 + lc);
        Ks[lc+0][lr]=kv.x; Ks[lc+1][lr]=kv.y; Ks[lc+2][lr]=kv.z; Ks[lc+3][lr]=kv.w;
        if (tid < 50) {
            int qr = tid >> 1;
            float4 qv = ldh4(g_Qh + ((size_t)g*25 + qr)*HDp + k0 + lc);
            Qs[lc+0][qr]=qv.x; Qs[lc+1][qr]=qv.y; Qs[lc+2][qr]=qv.z; Qs[lc+3][qr]=qv.w;
        }
        __syncthreads();
        #pragma unroll
        for (int kk = 0; kk < 8; kk++) {
            float bvv = Ks[kk][col];
            #pragma unroll
            for (int i = 0; i < 13; i++) {
                int r = rg + 2*i;
                if (r < 25) acc[i] = fmaf(Qs[kk][r], bvv, acc[i]);
            }
        }
        __syncthreads();
    }
    const float scale = rsqrtf((float)HDp);
    float bias = g_bias[b*SEQ + bn + col];
    #pragma unroll
    for (int i = 0; i < 13; i++) {
        int r = rg + 2*i;
        if (r < 25)
            g_Ph[((size_t)g*25 + r)*SEQ + bn + col] = __float2half_rn(acc[i]*scale + bias);
    }
}

// ---------------- warp-per-row softmax over g_Ph -------------------------------
__global__ void softmax_rows(int nrows)
{
    int row = blockIdx.x * 8 + (threadIdx.x >> 5);
    if (row >= nrows) return;
    int lane = threadIdx.x & 31;
    __half* p = g_Ph + (size_t)row * SEQ + lane * 16;
    uint4 u0 = *(const uint4*)(p);
    uint4 u1 = *(const uint4*)(p + 8);
    float v[16];
    {
        const uint32_t* w0 = (const uint32_t*)&u0;
        const uint32_t* w1 = (const uint32_t*)&u1;
        #pragma unroll
        for (int i = 0; i < 4; i++) {
            float2 a = __half22float2(*(const __half2*)&w0[i]);
            float2 b = __half22float2(*(const __half2*)&w1[i]);
            v[2*i]   = a.x; v[2*i+1]   = a.y;
            v[8+2*i] = b.x; v[8+2*i+1] = b.y;
        }
    }
    float m = v[0];
    #pragma unroll
    for (int i = 1; i < 16; i++) m = fmaxf(m, v[i]);
    #pragma unroll
    for (int off = 16; off > 0; off >>= 1)
        m = fmaxf(m, __shfl_xor_sync(0xffffffffu, m, off));
    float s = 0.f;
    #pragma unroll
    for (int i = 0; i < 16; i++) { v[i] = expf(v[i] - m); s += v[i]; }
    #pragma unroll
    for (int off = 16; off > 0; off >>= 1)
        s += __shfl_xor_sync(0xffffffffu, s, off);
    float inv = 1.f / s;
    uint4 o0, o1;
    {
        uint32_t* w0 = (uint32_t*)&o0;
        uint32_t* w1 = (uint32_t*)&o1;
        #pragma unroll
        for (int i = 0; i < 4; i++) {
            __half2 a = __floats2half2_rn(v[2*i]*inv,   v[2*i+1]*inv);
            __half2 b = __floats2half2_rn(v[8+2*i]*inv, v[8+2*i+1]*inv);
            w0[i] = *(uint32_t*)&a;
            w1[i] = *(uint32_t*)&b;
        }
    }
    *(uint4*)(p)     = o0;
    *(uint4*)(p + 8) = o1;
}

// ---------------- layer-2 compact O = P @ V -------------------------------------
__global__ void __launch_bounds__(160) gemm_av25()
{
    int blk = blockIdx.x;
    int g = blk / 25, r = blk % 25;
    int b = g >> 3, h = g & 7;
    __shared__ float Ps[512];
    const __half* prow = g_Ph + ((size_t)g*25 + r)*SEQ;
    int tid = threadIdx.x;
    for (int i = tid; i < SEQ; i += 160) Ps[i] = __half2float(prow[i]);
    __syncthreads();
    if (tid < HDp) {
        const __half* v = g_Vth + ((size_t)g*HDp + tid)*SEQ;
        float s = 0.f;
        #pragma unroll 4
        for (int t = 0; t < SEQ; t += 8) {
            uint4 u = *(const uint4*)(v + t);
            float2 f0 = __half22float2(*(__half2*)&u.x);
            float2 f1 = __half22float2(*(__half2*)&u.y);
            float2 f2 = __half22float2(*(__half2*)&u.z);
            float2 f3 = __half22float2(*(__half2*)&u.w);
            s = fmaf(Ps[t],   f0.x, s); s = fmaf(Ps[t+1], f0.y, s);
            s = fmaf(Ps[t+2], f1.x, s); s = fmaf(Ps[t+3], f1.y, s);
            s = fmaf(Ps[t+4], f2.x, s); s = fmaf(Ps[t+5], f2.y, s);
            s = fmaf(Ps[t+6], f3.x, s); s = fmaf(Ps[t+7], f3.y, s);
        }
        g_ATTh[((size_t)b*25 + r)*DMp + h*HDp + tid] = __float2half_rn(s);
    }
}

// ---------------- residual add + layernorm (o is fp32) --------------------------
__global__ void add_ln(float* __restrict__ x, __half* __restrict__ xh,
                       const float* __restrict__ o,
                       const float* __restrict__ w, const float* __restrict__ bb)
{
    size_t row = blockIdx.x;
    float* xr = x + row * DMp;
    __half* xhr = xh + row * DMp;
    const float* orow = o + row * DMp;
    int tid = threadIdx.x;
    float vals[5];
    int cnt = 0;
    float s = 0.f;
    for (int i = tid; i < DMp; i += 256) { float v = xr[i] + orow[i]; vals[cnt++] = v; s += v; }
    __shared__ float red[256];
    red[tid] = s; __syncthreads();
    for (int st = 128; st > 0; st >>= 1) { if (tid < st) red[tid] += red[tid + st]; __syncthreads(); }
    float mu = red[0] * (1.f / DMp);
    __syncthreads();
    float s2 = 0.f;
    for (int k = 0; k < cnt; k++) { float d = vals[k] - mu; s2 += d * d; }
    red[tid] = s2; __syncthreads();
    for (int st = 128; st > 0; st >>= 1) { if (tid < st) red[tid] += red[tid + st]; __syncthreads(); }
    float rstd = rsqrtf(red[0] * (1.f / DMp) + 1e-5f);
    int k = 0;
    for (int i = tid; i < DMp; i += 256, k++) {
        float r = (vals[k] - mu) * rstd * w[i] + bb[i];
        xr[i] = r;
        xhr[i] = __float2half_rn(r);
    }
}

// ---------------- gather outputs --------------------------------------------------
__global__ void gather_out(float* __restrict__ out)
{
    size_t idx = (size_t)blockIdx.x * blockDim.x + threadIdx.x;
    if (idx >= (size_t)Bsz * 25 * 1024) return;
    int c = (int)(idx % 1024);
    int rem = (int)(idx / 1024);
    int t = rem % 25;
    int b = rem / 25;
    float v = g_S2[((size_t)b*25 + t) * DMp + c];
    size_t o;
    if (t == 0)      o = (size_t)b * 1024 + c;
    else if (t < 13) o = (size_t)Bsz*1024 + ((size_t)b*12 + (t-1))*1024 + c;
    else             o = (size_t)Bsz*1024 + (size_t)Bsz*12*1024
                       + ((size_t)b*12 + (t-13))*1024 + c;
    out[o] = v;
}

// ---------------- launch ----------------------------------------------------------
extern "C" void kernel_launch(void* const* d_in, const int* in_sizes, int n_in,
                              void* d_out, int out_size)
{
    (void)in_sizes; (void)n_in; (void)out_size;
    const float* q    = (const float*)d_in[0];
    const float* sa   = (const float*)d_in[1];
    const float* si   = (const float*)d_in[2];
    const int*   na   = (const int*)  d_in[3];
    const int*   ni   = (const int*)  d_in[4];
    const float* ref  = (const float*)d_in[5];
    const float* Wqkv = (const float*)d_in[6];
    const float* bqkv = (const float*)d_in[7];
    const float* Wo   = (const float*)d_in[8];
    const float* bo   = (const float*)d_in[9];
    const float* ln1w = (const float*)d_in[10];
    const float* ln1b = (const float*)d_in[11];
    const float* W1   = (const float*)d_in[12];
    const float* b1   = (const float*)d_in[13];
    const float* W2   = (const float*)d_in[14];
    const float* b2   = (const float*)d_in[15];
    const float* ln2w = (const float*)d_in[16];
    const float* ln2b = (const float*)d_in[17];

    float *S, *O, *S2, *O2;
    __half *Sh, *QKVh, *ATTh, *FFNh, *S2h, *Wqkvh, *Woh, *W1h, *W2h, *Qh;
    cudaGetSymbolAddress((void**)&S,    g_S);
    cudaGetSymbolAddress((void**)&Sh,   g_Sh);
    cudaGetSymbolAddress((void**)&QKVh, g_QKVh);
    cudaGetSymbolAddress((void**)&ATTh, g_ATTh);
    cudaGetSymbolAddress((void**)&FFNh, g_FFNh);
    cudaGetSymbolAddress((void**)&O,    g_O);
    cudaGetSymbolAddress((void**)&S2,   g_S2);
    cudaGetSymbolAddress((void**)&S2h,  g_S2h);
    cudaGetSymbolAddress((void**)&O2,   g_O2);
    cudaGetSymbolAddress((void**)&Qh,   g_Qh);
    cudaGetSymbolAddress((void**)&Wqkvh, g_Wqkvh);
    cudaGetSymbolAddress((void**)&Woh,   g_Woh);
    cudaGetSymbolAddress((void**)&W1h,   g_W1h);
    cudaGetSymbolAddress((void**)&W2h,   g_W2h);

    cudaFuncSetAttribute(gemm_nt_h,      cudaFuncAttributeMaxDynamicSharedMemorySize, TCSMEM);
    cudaFuncSetAttribute(gemm_scores_tc, cudaFuncAttributeMaxDynamicSharedMemorySize, TCSMEM);
    cudaFuncSetAttribute(gemm_av_tc,     cudaFuncAttributeMaxDynamicSharedMemorySize, TCSMEM);

    // weight conversion (f32 -> f16)
    {
        int n;
        n = Ll*3*DMp*DMp/4; cvt_f2h<<<(n+255)/256, 256>>>((const float4*)Wqkv, Wqkvh, n);
        n = Ll*DMp*DMp/4;   cvt_f2h<<<(n+255)/256, 256>>>((const float4*)Wo,   Woh,   n);
        n = Ll*DFFp*DMp/4;  cvt_f2h<<<(n+255)/256, 256>>>((const float4*)W1,   W1h,   n);
        n = Ll*DMp*DFFp/4;  cvt_f2h<<<(n+255)/256, 256>>>((const float4*)W2,   W2h,   n);
    }

    const int elems = MROWS * DMp;
    build_S<<<elems/256, 256>>>(q, sa, si, ref, na, ni);

    // ===================== Layer 0: full 512-token path =====================
    {
        // QKV projection with fused Q/K scatter; V lands packed in QKVh
        gemm_nt_h<<<dim3((3*DMp + 127)/128, MROWS/128), 256, TCSMEM>>>(Sh, Wqkvh, bqkv, QKVh, MROWS, 3*DMp, DMp, 0, MODE_QKV1);
        transpose_v<<<dim3(SEQ/32, (HDp + 31)/32, GHEADS), dim3(32, 8)>>>(3*DMp, 2*DMp);
        gemm_scores_tc<<<dim3(SEQ/128, SEQ/128, GHEADS), 256, TCSMEM>>>();
        softmax_rows<<<(GHEADS*SEQ + 7)/8, 256>>>(GHEADS*SEQ);
        gemm_av_tc<<<dim3((HDp + 127)/128, SEQ/128, GHEADS), 256, TCSMEM>>>();
        gemm_nt_h<<<dim3((DMp + 127)/128, MROWS/128), 256, TCSMEM>>>(ATTh, Woh, bo, O, MROWS, DMp, DMp, 0, MODE_DENSE_F);
        add_ln<<<MROWS, 256>>>(S, Sh, O, ln1w, ln1b);
        gemm_nt_h<<<dim3(DFFp/128, MROWS/128), 256, TCSMEM>>>(Sh, W1h, b1, FFNh, MROWS, DFFp, DMp, 1, MODE_DENSE_H);
        gemm_nt_h<<<dim3((DMp + 127)/128, MROWS/128), 256, TCSMEM>>>(FFNh, W2h, b2, O, MROWS, DMp, DFFp, 0, MODE_DENSE_F);
        add_ln<<<MROWS, 256>>>(S, Sh, O, ln2w, ln2b);
    }

    // ===================== Layer 1: pruned 25-token path =====================
    {
        const __half* wqkvh = Wqkvh + (size_t)1 * 3 * DMp * DMp;
        const float*  bq    = bqkv  + (size_t)1 * 3 * DMp;
        // KV projection with fused K scatter; V packed in QKVh (rowW 2*DMp)
        gemm_nt_h<<<dim3((2*DMp + 127)/128, MROWS/128), 256, TCSMEM>>>(Sh, wqkvh + (size_t)DMp*DMp, bq + DMp, QKVh, MROWS, 2*DMp, DMp, 0, MODE_KV2);
        transpose_v<<<dim3(SEQ/32, (HDp + 31)/32, GHEADS), dim3(32, 8)>>>(2*DMp, DMp);
        gather_S2<<<(M2*DMp + 255)/256, 256>>>();
        // compact Q projection with fused scatter into g_Qh (stride 25)
        gemm_nt_h<<<dim3((DMp + 127)/128, (M2 + 127)/128), 256, TCSMEM>>>(S2h, wqkvh, bq, Qh, M2, DMp, DMp, 0, MODE_Q25);
        gemm_scores25<<<dim3(SEQ/128, GHEADS), 256>>>();
        softmax_rows<<<(GHEADS*25 + 7)/8, 256>>>(GHEADS*25);
        gemm_av25<<<GHEADS*25, 160>>>();
        gemm_nt_h<<<dim3((DMp + 127)/128, (M2 + 127)/128), 256, TCSMEM>>>(ATTh, Woh + (size_t)DMp*DMp, bo + DMp, O2, M2, DMp, DMp, 0, MODE_DENSE_F);
        add_ln<<<M2, 256>>>(S2, S2h, O2, ln1w + DMp, ln1b + DMp);
        gemm_nt_h<<<dim3(DFFp/128, (M2 + 127)/128), 256, TCSMEM>>>(S2h, W1h + (size_t)DFFp*DMp, b1 + DFFp, FFNh, M2, DFFp, DMp, 1, MODE_DENSE_H);
        gemm_nt_h<<<dim3((DMp + 127)/128, (M2 + 127)/128), 256, TCSMEM>>>(FFNh, W2h + (size_t)DMp*DFFp, b2 + DMp, O2, M2, DMp, DFFp, 0, MODE_DENSE_F);
        add_ln<<<M2, 256>>>(S2, S2h, O2, ln2w + DMp, ln2b + DMp);
    }

    gather_out<<<(Bsz*25*1024)/256, 256>>>((float*)d_out);
}

// round 16
// speedup vs baseline: 1.0545x; 1.0080x over previous
#include <cuda_runtime.h>
#include <cuda_fp16.h>
#include <math.h>
#include <stdint.h>

#define Bsz   64
#define Dd    1024
#define DMp   1088
#define Hh    8
#define HDp   136
#define DFFp  2048
#define SEQ   512
#define Rr    487
#define MROWS (Bsz*SEQ)     /* 32768 */
#define GHEADS (Bsz*Hh)     /* 512  */
#define M2    (Bsz*25)      /* 1600 */
#define Ll    2

// ---------------- scratch (device globals) -----------------------------------
__device__ __half g_Sh [(size_t)MROWS*DMp];       // fp16 residual chain (layer 0)
__device__ __half g_QKVh[(size_t)MROWS*3*DMp];
__device__ __half g_Qh [(size_t)GHEADS*SEQ*HDp];
__device__ __half g_Kh [(size_t)GHEADS*SEQ*HDp];
__device__ __half g_Vth[(size_t)GHEADS*HDp*SEQ];
__device__ __half g_Ph [(size_t)GHEADS*SEQ*SEQ];
__device__ __half g_ATTh[(size_t)MROWS*DMp];
__device__ __half g_FFNh[(size_t)MROWS*DFFp];
__device__ __half g_Oh [(size_t)MROWS*DMp];
__device__ float  g_S2 [(size_t)M2*DMp];          // f32 compact chain (layer 1)
__device__ __half g_S2h[(size_t)M2*DMp];
__device__ float  g_O2 [(size_t)M2*DMp];
__device__ float  g_bias[Bsz*SEQ];
__device__ __half g_Wqkvh[(size_t)Ll*3*DMp*DMp];
__device__ __half g_Woh  [(size_t)Ll*DMp*DMp];
__device__ __half g_W1h  [(size_t)Ll*DFFp*DMp];
__device__ __half g_W2h  [(size_t)Ll*DMp*DFFp];

// epilogue modes
#define MODE_DENSE_H 0
#define MODE_DENSE_F 1
#define MODE_QKV1    2
#define MODE_KV2     3
#define MODE_Q25     4

// ---------------- f32 -> f16 convert ------------------------------------------
__global__ void cvt_f2h(const float4* __restrict__ s, __half* __restrict__ d, int n4)
{
    int i = blockIdx.x * blockDim.x + threadIdx.x;
    if (i >= n4) return;
    float4 v = s[i];
    union { __half2 h; uint32_t u; } p0, p1;
    p0.h = __floats2half2_rn(v.x, v.y);
    p1.h = __floats2half2_rn(v.z, v.w);
    *(uint2*)(d + (size_t)i*4) = make_uint2(p0.u, p1.u);
}

// ---------------- build S tensor (fp16 only) + mask bias ------------------------
__global__ void build_S(const float* __restrict__ q, const float* __restrict__ sa,
                        const float* __restrict__ si, const float* __restrict__ ref,
                        const int* __restrict__ na, const int* __restrict__ ni)
{
    size_t idx = (size_t)blockIdx.x * blockDim.x + threadIdx.x;
    if (idx >= (size_t)MROWS * DMp) return;
    int c = (int)(idx % DMp);
    size_t row = idx / DMp;
    int t = (int)(row % SEQ);
    int b = (int)(row / SEQ);
    float v;
    if (t == 0)       v = (c < Dd) ? q  [(size_t)b*Dd + c]              : 0.f;
    else if (t < 13)  v = (c < Dd) ? sa [((size_t)b*12 + (t-1))*Dd + c] : 1.f;
    else if (t < 25)  v = (c < Dd) ? si [((size_t)b*12 + (t-13))*Dd + c]: -1.f;
    else              v = (c < Dd) ? ref[((size_t)b*Rr + (t-25))*Dd + c]: 0.f;
    g_Sh[idx] = __float2half_rn(v);
    if (c == 0) {
        int ra = na[b], ri = ni[b];
        bool m = (t == 0)
              || (t >= 1  && t < 13 && t < ra + 1)
              || (t >= 13 && t < 25 && t < ri + 13);
        g_bias[b*SEQ + t] = m ? -1.0e9f : 0.f;
    }
}

// ================= fp16 tensor-core GEMM engine ==============================
#define SMKH 24
#define NSTG 4
#define TCSMEM (2 * NSTG * 128 * SMKH * 2)   /* 49152 B */

typedef __half TcTile[128][SMKH];

__device__ __forceinline__ uint32_t smem_u32(const void* p) {
    return (uint32_t)__cvta_generic_to_shared(p);
}

__device__ __forceinline__ void cpa16(uint32_t dst, const __half* src, bool pred) {
    int sz = pred ? 16 : 0;
    asm volatile("cp.async.cg.shared.global [%0], [%1], 16, %2;\n"
                 :: "r"(dst), "l"(src), "r"(sz));
}
#define CP_COMMIT() asm volatile("cp.async.commit_group;\n" ::)
#define CP_WAIT(N)  asm volatile("cp.async.wait_group %0;\n" :: "n"(N))

#define LDSM_X4(r0,r1,r2,r3,addr) \
    asm volatile("ldmatrix.sync.aligned.m8n8.x4.shared.b16 {%0,%1,%2,%3}, [%4];" \
                 : "=r"(r0),"=r"(r1),"=r"(r2),"=r"(r3) : "r"(addr))

__device__ __forceinline__ void mma_f16(float (&d)[4], const uint32_t (&a)[4],
                                        const uint32_t (&b)[2]) {
    asm volatile(
        "mma.sync.aligned.m16n8k16.row.col.f32.f16.f16.f32 "
        "{%0,%1,%2,%3}, {%4,%5,%6,%7}, {%8,%9}, {%0,%1,%2,%3};"
        : "+f"(d[0]), "+f"(d[1]), "+f"(d[2]), "+f"(d[3])
        : "r"(a[0]), "r"(a[1]), "r"(a[2]), "r"(a[3]), "r"(b[0]), "r"(b[1]));
}

__device__ __forceinline__ void tc4_step(
    float (&acc)[4][4][4], const TcTile& As, const TcTile& Bs,
    int mb, int nb, int lane)
{
    uint32_t b[4][2];
    {
        int row = nb + ((lane >> 4) << 3) + (lane & 7);
        int kh  = ((lane >> 3) & 1) * 8;
        LDSM_X4(b[0][0], b[0][1], b[1][0], b[1][1], smem_u32(&Bs[row][kh]));
        LDSM_X4(b[2][0], b[2][1], b[3][0], b[3][1], smem_u32(&Bs[row + 16][kh]));
    }
    int arow = (lane & 15);
    int akh  = (lane >> 4) * 8;
    #pragma unroll
    for (int mi = 0; mi < 4; mi++) {
        uint32_t a[4];
        LDSM_X4(a[0], a[1], a[2], a[3], smem_u32(&As[mb + mi*16 + arow][akh]));
        #pragma unroll
        for (int ni = 0; ni < 4; ni++)
            mma_f16(acc[mi][ni], a, b[ni]);
    }
}

__device__ __forceinline__ void tc4_loop_f16(
    const __half* __restrict__ A, const __half* __restrict__ Bw,
    int K, int M, int N, int bm, int bn,
    float (&acc)[4][4][4], TcTile* As, TcTile* Bs, int tid)
{
    int lane = tid & 31, wid = tid >> 5;
    int mb = (wid >> 2) * 64, nb = (wid & 3) * 32;
    int rr = tid >> 1;
    int lch = (tid & 1) * 8;

    int ar = bm + rr, br = bn + rr;
    bool av = ar < M, bv = br < N;
    const __half* Aprow = A  + (size_t)(av ? ar : 0) * K + lch;
    const __half* Bprow = Bw + (size_t)(bv ? br : 0) * K + lch;

    int chunks = (K + 15) / 16;

    #pragma unroll
    for (int s = 0; s < 3; s++) {
        int k0 = s * 16;
        bool kok = (k0 + lch) < K;
        cpa16(smem_u32(&As[s][rr][lch]), Aprow + k0, kok && av);
        cpa16(smem_u32(&Bs[s][rr][lch]), Bprow + k0, kok && bv);
        CP_COMMIT();
    }

    int buf = 0;
    for (int c = 0; c < chunks; c++) {
        if (c + 1 >= chunks)      { CP_WAIT(0); }
        else if (c + 2 >= chunks) { CP_WAIT(1); }
        else                      { CP_WAIT(2); }
        __syncthreads();
        int kn = (c + 3) * 16;
        if (kn < K) {
            bool kok = (kn + lch) < K;
            int nbuf = (buf + 3) & 3;
            cpa16(smem_u32(&As[nbuf][rr][lch]), Aprow + kn, kok && av);
            cpa16(smem_u32(&Bs[nbuf][rr][lch]), Bprow + kn, kok && bv);
            CP_COMMIT();
        }
        tc4_step(acc, As[buf], Bs[buf], mb, nb, lane);
        buf = (buf + 1) & 3;
    }
}

// ---------------- scatter store helper for fused unpack -------------------------
__device__ __forceinline__ void scatter_store(int mode, int row, int col,
                                              __half2 val, __half* Cv)
{
    int t, b;
    if (mode == MODE_Q25) { t = row % 25; b = row / 25; }
    else                  { t = row & (SEQ - 1); b = row >> 9; }
    if (mode == MODE_QKV1) {
        if (col < DMp) {
            int h = col / HDp, d = col - h * HDp;
            *(__half2*)(g_Qh + ((size_t)(b*Hh + h)*SEQ + t)*HDp + d) = val;
        } else if (col < 2*DMp) {
            int c = col - DMp;
            int h = c / HDp, d = c - h * HDp;
            *(__half2*)(g_Kh + ((size_t)(b*Hh + h)*SEQ + t)*HDp + d) = val;
        } else {
            *(__half2*)(Cv + (size_t)row * (3*DMp) + col) = val;
        }
    } else if (mode == MODE_KV2) {
        if (col < DMp) {
            int h = col / HDp, d = col - h * HDp;
            *(__half2*)(g_Kh + ((size_t)(b*Hh + h)*SEQ + t)*HDp + d) = val;
        } else {
            *(__half2*)(Cv + (size_t)row * (2*DMp) + col) = val;
        }
    } else {  // MODE_Q25
        int h = col / HDp, d = col - h * HDp;
        *(__half2*)(g_Qh + ((size_t)(b*Hh + h)*25 + t)*HDp + d) = val;
    }
}

// ---------------- generic fp16 GEMM with fused-scatter epilogue -----------------
__global__ void __launch_bounds__(256, 2)
gemm_nt_h(const __half* __restrict__ A, const __half* __restrict__ Bw,
          const float* __restrict__ bias, void* __restrict__ Cv,
          int M, int N, int K, int relu, int mode)
{
    extern __shared__ __align__(16) char dsm[];
    TcTile* As = reinterpret_cast<TcTile*>(dsm);
    TcTile* Bs = reinterpret_cast<TcTile*>(dsm + NSTG * 128 * SMKH * 2);
    int tid = threadIdx.x, lane = tid & 31, wid = tid >> 5;
    int mb = (wid >> 2) * 64, nb = (wid & 3) * 32;
    int gid = lane >> 2, tig = lane & 3;
    int bm = blockIdx.y * 128, bn = blockIdx.x * 128;
    float acc[4][4][4] = {};
    tc4_loop_f16(A, Bw, K, M, N, bm, bn, acc, As, Bs, tid);
    #pragma unroll
    for (int mi = 0; mi < 4; mi++) {
        int row = bm + mb + mi*16 + gid;
        #pragma unroll
        for (int ni = 0; ni < 4; ni++) {
            int col = bn + nb + ni*8 + tig*2;
            if (col >= N) continue;
            float b0 = bias[col], b1 = bias[col+1];
            float v0 = acc[mi][ni][0] + b0, v1 = acc[mi][ni][1] + b1;
            float v2 = acc[mi][ni][2] + b0, v3 = acc[mi][ni][3] + b1;
            if (relu) {
                v0 = fmaxf(v0, 0.f); v1 = fmaxf(v1, 0.f);
                v2 = fmaxf(v2, 0.f); v3 = fmaxf(v3, 0.f);
            }
            if (mode == MODE_DENSE_H) {
                __half* C = (__half*)Cv;
                if (row < M)     *(__half2*)(C + (size_t)row * N + col)       = __floats2half2_rn(v0, v1);
                if (row + 8 < M) *(__half2*)(C + (size_t)(row + 8) * N + col) = __floats2half2_rn(v2, v3);
            } else if (mode == MODE_DENSE_F) {
                float* C = (float*)Cv;
                if (row < M)     *(float2*)(C + (size_t)row * N + col)       = make_float2(v0, v1);
                if (row + 8 < M) *(float2*)(C + (size_t)(row + 8) * N + col) = make_float2(v2, v3);
            } else {
                if (row < M)     scatter_store(mode, row,     col, __floats2half2_rn(v0, v1), (__half*)Cv);
                if (row + 8 < M) scatter_store(mode, row + 8, col, __floats2half2_rn(v2, v3), (__half*)Cv);
            }
        }
    }
}

// ---------------- layer-1 scores: Ph = f16(scale*Q@K^T + bias) ---------------
__global__ void __launch_bounds__(256, 2) gemm_scores_tc()
{
    extern __shared__ __align__(16) char dsm[];
    TcTile* As = reinterpret_cast<TcTile*>(dsm);
    TcTile* Bs = reinterpret_cast<TcTile*>(dsm + NSTG * 128 * SMKH * 2);
    int g = blockIdx.z, b = g >> 3;
    const __half* A  = g_Qh + (size_t)g * SEQ * HDp;
    const __half* Bw = g_Kh + (size_t)g * SEQ * HDp;
    __half* C = g_Ph + (size_t)g * SEQ * SEQ;
    int tid = threadIdx.x, lane = tid & 31, wid = tid >> 5;
    int mb = (wid >> 2) * 64, nb = (wid & 3) * 32;
    int gid = lane >> 2, tig = lane & 3;
    int bm = blockIdx.y * 128, bn = blockIdx.x * 128;
    float acc[4][4][4] = {};
    tc4_loop_f16(A, Bw, HDp, SEQ, SEQ, bm, bn, acc, As, Bs, tid);
    const float scale = rsqrtf((float)HDp);
    #pragma unroll
    for (int mi = 0; mi < 4; mi++) {
        int row = bm + mb + mi*16 + gid;
        #pragma unroll
        for (int ni = 0; ni < 4; ni++) {
            int col = bn + nb + ni*8 + tig*2;
            float b0 = g_bias[b*SEQ + col], b1 = g_bias[b*SEQ + col + 1];
            *(__half2*)(C + (size_t)row * SEQ + col) =
                __floats2half2_rn(acc[mi][ni][0]*scale + b0, acc[mi][ni][1]*scale + b1);
            *(__half2*)(C + (size_t)(row+8) * SEQ + col) =
                __floats2half2_rn(acc[mi][ni][2]*scale + b0, acc[mi][ni][3]*scale + b1);
        }
    }
}

// ---------------- layer-1 O = P @ V -> fp16 ATTh -------------------------------
__global__ void __launch_bounds__(256, 2) gemm_av_tc()
{
    extern __shared__ __align__(16) char dsm[];
    TcTile* As = reinterpret_cast<TcTile*>(dsm);
    TcTile* Bs = reinterpret_cast<TcTile*>(dsm + NSTG * 128 * SMKH * 2);
    int g = blockIdx.z, b = g >> 3, h = g & 7;
    const __half* A  = g_Ph  + (size_t)g * SEQ * SEQ;
    const __half* Bw = g_Vth + (size_t)g * HDp * SEQ;
    int tid = threadIdx.x, lane = tid & 31, wid = tid >> 5;
    int mb = (wid >> 2) * 64, nb = (wid & 3) * 32;
    int gid = lane >> 2, tig = lane & 3;
    int bm = blockIdx.y * 128, bn = blockIdx.x * 128;
    float acc[4][4][4] = {};
    tc4_loop_f16(A, Bw, SEQ, SEQ, HDp, bm, bn, acc, As, Bs, tid);
    #pragma unroll
    for (int mi = 0; mi < 4; mi++) {
        int row = bm + mb + mi*16 + gid;
        #pragma unroll
        for (int ni = 0; ni < 4; ni++) {
            int col = bn + nb + ni*8 + tig*2;
            if (col >= HDp) continue;
            __half* base = g_ATTh + ((size_t)b*SEQ + row) * DMp + h*HDp + col;
            *(__half2*)(base) = __floats2half2_rn(acc[mi][ni][0], acc[mi][ni][1]);
            *(__half2*)(base + (size_t)8*DMp) = __floats2half2_rn(acc[mi][ni][2], acc[mi][ni][3]);
        }
    }
}

// ---------------- coalesced V transpose ----------------------------------------
__global__ void transpose_v(int rowW, int colOff)
{
    __shared__ __half tile[32][33];
    int gh = blockIdx.z;
    int b = gh >> 3, h = gh & 7;
    int t0 = blockIdx.x * 32, d0 = blockIdx.y * 32;
    int tx = threadIdx.x, ty = threadIdx.y;
    const __half* src = g_QKVh + (size_t)b * SEQ * rowW + colOff + h * HDp;
    #pragma unroll
    for (int i = 0; i < 4; i++) {
        int t = t0 + ty + i*8;
        int d = d0 + tx;
        if (d < HDp) tile[ty + i*8][tx] = src[(size_t)t * rowW + d];
    }
    __syncthreads();
    #pragma unroll
    for (int i = 0; i < 4; i++) {
        int d = d0 + ty + i*8;
        int t = t0 + tx;
        if (d < HDp) g_Vth[((size_t)gh*HDp + d)*SEQ + t] = tile[tx][ty + i*8];
    }
}

// ---------------- gather compact rows from fp16 Sh ------------------------------
__global__ void gather_S2()
{
    size_t idx = (size_t)blockIdx.x * blockDim.x + threadIdx.x;
    if (idx >= (size_t)M2 * DMp) return;
    int c = (int)(idx % DMp);
    int i = (int)(idx / DMp);
    int t = i % 25, b = i / 25;
    float v = __half2float(g_Sh[((size_t)b*SEQ + t)*DMp + c]);
    g_S2[idx]  = v;
    g_S2h[idx] = __float2half_rn(v);
}

__device__ __forceinline__ float4 ldh4(const __half* p) {
    uint2 u = *(const uint2*)p;
    float2 f0 = __half22float2(*(__half2*)&u.x), f1 = __half22float2(*(__half2*)&u.y);
    return make_float4(f0.x, f0.y, f1.x, f1.y);
}

// ---------------- layer-2 compact scores --------------------------------------
__global__ void __launch_bounds__(256) gemm_scores25()
{
    __shared__ float Qs[8][32];
    __shared__ float Ks[8][128];
    int g = blockIdx.y, b = g >> 3;
    int bn = blockIdx.x * 128;
    int tid = threadIdx.x;
    int lr = tid >> 1, lc = (tid & 1) * 4;
    int col = tid & 127, rg = tid >> 7;
    float acc[13];
    #pragma unroll
    for (int i = 0; i < 13; i++) acc[i] = 0.f;
    for (int k0 = 0; k0 < HDp; k0 += 8) {
        float4 kv = ldh4(g_Kh + ((size_t)g*SEQ + bn + lr)*HDp + k0 + lc);
        Ks[lc+0][lr]=kv.x; Ks[lc+1][lr]=kv.y; Ks[lc+2][lr]=kv.z; Ks[lc+3][lr]=kv.w;
        if (tid < 50) {
            int qr = tid >> 1;
            float4 qv = ldh4(g_Qh + ((size_t)g*25 + qr)*HDp + k0 + lc);
            Qs[lc+0][qr]=qv.x; Qs[lc+1][qr]=qv.y; Qs[lc+2][qr]=qv.z; Qs[lc+3][qr]=qv.w;
        }
        __syncthreads();
        #pragma unroll
        for (int kk = 0; kk < 8; kk++) {
            float bvv = Ks[kk][col];
            #pragma unroll
            for (int i = 0; i < 13; i++) {
                int r = rg + 2*i;
                if (r < 25) acc[i] = fmaf(Qs[kk][r], bvv, acc[i]);
            }
        }
        __syncthreads();
    }
    const float scale = rsqrtf((float)HDp);
    float bias = g_bias[b*SEQ + bn + col];
    #pragma unroll
    for (int i = 0; i < 13; i++) {
        int r = rg + 2*i;
        if (r < 25)
            g_Ph[((size_t)g*25 + r)*SEQ + bn + col] = __float2half_rn(acc[i]*scale + bias);
    }
}

// ---------------- warp-per-row softmax over g_Ph -------------------------------
__global__ void softmax_rows(int nrows)
{
    int row = blockIdx.x * 8 + (threadIdx.x >> 5);
    if (row >= nrows) return;
    int lane = threadIdx.x & 31;
    __half* p = g_Ph + (size_t)row * SEQ + lane * 16;
    uint4 u0 = *(const uint4*)(p);
    uint4 u1 = *(const uint4*)(p + 8);
    float v[16];
    {
        const uint32_t* w0 = (const uint32_t*)&u0;
        const uint32_t* w1 = (const uint32_t*)&u1;
        #pragma unroll
        for (int i = 0; i < 4; i++) {
            float2 a = __half22float2(*(const __half2*)&w0[i]);
            float2 b = __half22float2(*(const __half2*)&w1[i]);
            v[2*i]   = a.x; v[2*i+1]   = a.y;
            v[8+2*i] = b.x; v[8+2*i+1] = b.y;
        }
    }
    float m = v[0];
    #pragma unroll
    for (int i = 1; i < 16; i++) m = fmaxf(m, v[i]);
    #pragma unroll
    for (int off = 16; off > 0; off >>= 1)
        m = fmaxf(m, __shfl_xor_sync(0xffffffffu, m, off));
    float s = 0.f;
    #pragma unroll
    for (int i = 0; i < 16; i++) { v[i] = expf(v[i] - m); s += v[i]; }
    #pragma unroll
    for (int off = 16; off > 0; off >>= 1)
        s += __shfl_xor_sync(0xffffffffu, s, off);
    float inv = 1.f / s;
    uint4 o0, o1;
    {
        uint32_t* w0 = (uint32_t*)&o0;
        uint32_t* w1 = (uint32_t*)&o1;
        #pragma unroll
        for (int i = 0; i < 4; i++) {
            __half2 a = __floats2half2_rn(v[2*i]*inv,   v[2*i+1]*inv);
            __half2 b = __floats2half2_rn(v[8+2*i]*inv, v[8+2*i+1]*inv);
            w0[i] = *(uint32_t*)&a;
            w1[i] = *(uint32_t*)&b;
        }
    }
    *(uint4*)(p)     = o0;
    *(uint4*)(p + 8) = o1;
}

// ---------------- layer-2 compact O = P @ V -------------------------------------
__global__ void __launch_bounds__(160) gemm_av25()
{
    int blk = blockIdx.x;
    int g = blk / 25, r = blk % 25;
    int b = g >> 3, h = g & 7;
    __shared__ float Ps[512];
    const __half* prow = g_Ph + ((size_t)g*25 + r)*SEQ;
    int tid = threadIdx.x;
    for (int i = tid; i < SEQ; i += 160) Ps[i] = __half2float(prow[i]);
    __syncthreads();
    if (tid < HDp) {
        const __half* v = g_Vth + ((size_t)g*HDp + tid)*SEQ;
        float s = 0.f;
        #pragma unroll 4
        for (int t = 0; t < SEQ; t += 8) {
            uint4 u = *(const uint4*)(v + t);
            float2 f0 = __half22float2(*(__half2*)&u.x);
            float2 f1 = __half22float2(*(__half2*)&u.y);
            float2 f2 = __half22float2(*(__half2*)&u.z);
            float2 f3 = __half22float2(*(__half2*)&u.w);
            s = fmaf(Ps[t],   f0.x, s); s = fmaf(Ps[t+1], f0.y, s);
            s = fmaf(Ps[t+2], f1.x, s); s = fmaf(Ps[t+3], f1.y, s);
            s = fmaf(Ps[t+4], f2.x, s); s = fmaf(Ps[t+5], f2.y, s);
            s = fmaf(Ps[t+6], f3.x, s); s = fmaf(Ps[t+7], f3.y, s);
        }
        g_ATTh[((size_t)b*25 + r)*DMp + h*HDp + tid] = __float2half_rn(s);
    }
}

// ---------------- layer-0 residual add + LN (fp16 chain) ------------------------
__global__ void add_ln_h(__half* __restrict__ xh, const __half* __restrict__ o,
                         const float* __restrict__ w, const float* __restrict__ bb)
{
    size_t row = blockIdx.x;
    __half* xr = xh + row * DMp;
    const __half* orow = o + row * DMp;
    int tid = threadIdx.x;
    float vals[5];
    int cnt = 0;
    float s = 0.f;
    for (int i = tid; i < DMp; i += 256) {
        float v = __half2float(xr[i]) + __half2float(orow[i]);
        vals[cnt++] = v; s += v;
    }
    __shared__ float red[256];
    red[tid] = s; __syncthreads();
    for (int st = 128; st > 0; st >>= 1) { if (tid < st) red[tid] += red[tid + st]; __syncthreads(); }
    float mu = red[0] * (1.f / DMp);
    __syncthreads();
    float s2 = 0.f;
    for (int k = 0; k < cnt; k++) { float d = vals[k] - mu; s2 += d * d; }
    red[tid] = s2; __syncthreads();
    for (int st = 128; st > 0; st >>= 1) { if (tid < st) red[tid] += red[tid + st]; __syncthreads(); }
    float rstd = rsqrtf(red[0] * (1.f / DMp) + 1e-5f);
    int k = 0;
    for (int i = tid; i < DMp; i += 256, k++)
        xr[i] = __float2half_rn((vals[k] - mu) * rstd * w[i] + bb[i]);
}

// ---------------- layer-1 compact residual add + LN (fp32 chain) ----------------
__global__ void add_ln(float* __restrict__ x, __half* __restrict__ xh,
                       const float* __restrict__ o,
                       const float* __restrict__ w, const float* __restrict__ bb)
{
    size_t row = blockIdx.x;
    float* xr = x + row * DMp;
    __half* xhr = xh + row * DMp;
    const float* orow = o + row * DMp;
    int tid = threadIdx.x;
    float vals[5];
    int cnt = 0;
    float s = 0.f;
    for (int i = tid; i < DMp; i += 256) { float v = xr[i] + orow[i]; vals[cnt++] = v; s += v; }
    __shared__ float red[256];
    red[tid] = s; __syncthreads();
    for (int st = 128; st > 0; st >>= 1) { if (tid < st) red[tid] += red[tid + st]; __syncthreads(); }
    float mu = red[0] * (1.f / DMp);
    __syncthreads();
    float s2 = 0.f;
    for (int k = 0; k < cnt; k++) { float d = vals[k] - mu; s2 += d * d; }
    red[tid] = s2; __syncthreads();
    for (int st = 128; st > 0; st >>= 1) { if (tid < st) red[tid] += red[tid + st]; __syncthreads(); }
    float rstd = rsqrtf(red[0] * (1.f / DMp) + 1e-5f);
    int k = 0;
    for (int i = tid; i < DMp; i += 256, k++) {
        float r = (vals[k] - mu) * rstd * w[i] + bb[i];
        xr[i] = r;
        xhr[i] = __float2half_rn(r);
    }
}

// ---------------- gather outputs --------------------------------------------------
__global__ void gather_out(float* __restrict__ out)
{
    size_t idx = (size_t)blockIdx.x * blockDim.x + threadIdx.x;
    if (idx >= (size_t)Bsz * 25 * 1024) return;
    int c = (int)(idx % 1024);
    int rem = (int)(idx / 1024);
    int t = rem % 25;
    int b = rem / 25;
    float v = g_S2[((size_t)b*25 + t) * DMp + c];
    size_t o;
    if (t == 0)      o = (size_t)b * 1024 + c;
    else if (t < 13) o = (size_t)Bsz*1024 + ((size_t)b*12 + (t-1))*1024 + c;
    else             o = (size_t)Bsz*1024 + (size_t)Bsz*12*1024
                       + ((size_t)b*12 + (t-13))*1024 + c;
    out[o] = v;
}

// ---------------- launch ----------------------------------------------------------
extern "C" void kernel_launch(void* const* d_in, const int* in_sizes, int n_in,
                              void* d_out, int out_size)
{
    (void)in_sizes; (void)n_in; (void)out_size;
    const float* q    = (const float*)d_in[0];
    const float* sa   = (const float*)d_in[1];
    const float* si   = (const float*)d_in[2];
    const int*   na   = (const int*)  d_in[3];
    const int*   ni   = (const int*)  d_in[4];
    const float* ref  = (const float*)d_in[5];
    const float* Wqkv = (const float*)d_in[6];
    const float* bqkv = (const float*)d_in[7];
    const float* Wo   = (const float*)d_in[8];
    const float* bo   = (const float*)d_in[9];
    const float* ln1w = (const float*)d_in[10];
    const float* ln1b = (const float*)d_in[11];
    const float* W1   = (const float*)d_in[12];
    const float* b1   = (const float*)d_in[13];
    const float* W2   = (const float*)d_in[14];
    const float* b2   = (const float*)d_in[15];
    const float* ln2w = (const float*)d_in[16];
    const float* ln2b = (const float*)d_in[17];

    float *S2, *O2;
    __half *Sh, *QKVh, *ATTh, *FFNh, *Oh, *S2h, *Wqkvh, *Woh, *W1h, *W2h, *Qh;
    cudaGetSymbolAddress((void**)&Sh,   g_Sh);
    cudaGetSymbolAddress((void**)&QKVh, g_QKVh);
    cudaGetSymbolAddress((void**)&ATTh, g_ATTh);
    cudaGetSymbolAddress((void**)&FFNh, g_FFNh);
    cudaGetSymbolAddress((void**)&Oh,   g_Oh);
    cudaGetSymbolAddress((void**)&S2,   g_S2);
    cudaGetSymbolAddress((void**)&S2h,  g_S2h);
    cudaGetSymbolAddress((void**)&O2,   g_O2);
    cudaGetSymbolAddress((void**)&Qh,   g_Qh);
    cudaGetSymbolAddress((void**)&Wqkvh, g_Wqkvh);
    cudaGetSymbolAddress((void**)&Woh,   g_Woh);
    cudaGetSymbolAddress((void**)&W1h,   g_W1h);
    cudaGetSymbolAddress((void**)&W2h,   g_W2h);

    cudaFuncSetAttribute(gemm_nt_h,      cudaFuncAttributeMaxDynamicSharedMemorySize, TCSMEM);
    cudaFuncSetAttribute(gemm_scores_tc, cudaFuncAttributeMaxDynamicSharedMemorySize, TCSMEM);
    cudaFuncSetAttribute(gemm_av_tc,     cudaFuncAttributeMaxDynamicSharedMemorySize, TCSMEM);

    // weight conversion (f32 -> f16)
    {
        int n;
        n = Ll*3*DMp*DMp/4; cvt_f2h<<<(n+255)/256, 256>>>((const float4*)Wqkv, Wqkvh, n);
        n = Ll*DMp*DMp/4;   cvt_f2h<<<(n+255)/256, 256>>>((const float4*)Wo,   Woh,   n);
        n = Ll*DFFp*DMp/4;  cvt_f2h<<<(n+255)/256, 256>>>((const float4*)W1,   W1h,   n);
        n = Ll*DMp*DFFp/4;  cvt_f2h<<<(n+255)/256, 256>>>((const float4*)W2,   W2h,   n);
    }

    const int elems = MROWS * DMp;
    build_S<<<elems/256, 256>>>(q, sa, si, ref, na, ni);

    // ===================== Layer 0: full 512-token path (fp16 chain) ========
    {
        gemm_nt_h<<<dim3((3*DMp + 127)/128, MROWS/128), 256, TCSMEM>>>(Sh, Wqkvh, bqkv, QKVh, MROWS, 3*DMp, DMp, 0, MODE_QKV1);
        transpose_v<<<dim3(SEQ/32, (HDp + 31)/32, GHEADS), dim3(32, 8)>>>(3*DMp, 2*DMp);
        gemm_scores_tc<<<dim3(SEQ/128, SEQ/128, GHEADS), 256, TCSMEM>>>();
        softmax_rows<<<(GHEADS*SEQ + 7)/8, 256>>>(GHEADS*SEQ);
        gemm_av_tc<<<dim3((HDp + 127)/128, SEQ/128, GHEADS), 256, TCSMEM>>>();
        gemm_nt_h<<<dim3((DMp + 127)/128, MROWS/128), 256, TCSMEM>>>(ATTh, Woh, bo, Oh, MROWS, DMp, DMp, 0, MODE_DENSE_H);
        add_ln_h<<<MROWS, 256>>>(Sh, Oh, ln1w, ln1b);
        gemm_nt_h<<<dim3(DFFp/128, MROWS/128), 256, TCSMEM>>>(Sh, W1h, b1, FFNh, MROWS, DFFp, DMp, 1, MODE_DENSE_H);
        gemm_nt_h<<<dim3((DMp + 127)/128, MROWS/128), 256, TCSMEM>>>(FFNh, W2h, b2, Oh, MROWS, DMp, DFFp, 0, MODE_DENSE_H);
        add_ln_h<<<MROWS, 256>>>(Sh, Oh, ln2w, ln2b);
    }

    // ===================== Layer 1: pruned 25-token path (f32 compact) =======
    {
        const __half* wqkvh = Wqkvh + (size_t)1 * 3 * DMp * DMp;
        const float*  bq    = bqkv  + (size_t)1 * 3 * DMp;
        gemm_nt_h<<<dim3((2*DMp + 127)/128, MROWS/128), 256, TCSMEM>>>(Sh, wqkvh + (size_t)DMp*DMp, bq + DMp, QKVh, MROWS, 2*DMp, DMp, 0, MODE_KV2);
        transpose_v<<<dim3(SEQ/32, (HDp + 31)/32, GHEADS), dim3(32, 8)>>>(2*DMp, DMp);
        gather_S2<<<(M2*DMp + 255)/256, 256>>>();
        gemm_nt_h<<<dim3((DMp + 127)/128, (M2 + 127)/128), 256, TCSMEM>>>(S2h, wqkvh, bq, Qh, M2, DMp, DMp, 0, MODE_Q25);
        gemm_scores25<<<dim3(SEQ/128, GHEADS), 256>>>();
        softmax_rows<<<(GHEADS*25 + 7)/8, 256>>>(GHEADS*25);
        gemm_av25<<<GHEADS*25, 160>>>();
        gemm_nt_h<<<dim3((DMp + 127)/128, (M2 + 127)/128), 256, TCSMEM>>>(ATTh, Woh + (size_t)DMp*DMp, bo + DMp, O2, M2, DMp, DMp, 0, MODE_DENSE_F);
        add_ln<<<M2, 256>>>(S2, S2h, O2, ln1w + DMp, ln1b + DMp);
        gemm_nt_h<<<dim3(DFFp/128, (M2 + 127)/128), 256, TCSMEM>>>(S2h, W1h + (size_t)DFFp*DMp, b1 + DFFp, FFNh, M2, DFFp, DMp, 1, MODE_DENSE_H);
        gemm_nt_h<<<dim3((DMp + 127)/128, (M2 + 127)/128), 256, TCSMEM>>>(FFNh, W2h + (size_t)DMp*DFFp, b2 + DMp, O2, M2, DMp, DFFp, 0, MODE_DENSE_F);
        add_ln<<<M2, 256>>>(S2, S2h, O2, ln2w + DMp, ln2b + DMp);
    }

    gather_out<<<(Bsz*25*1024)/256, 256>>>((float*)d_out);
}